// round 13
// baseline (speedup 1.0000x reference)
#include <cuda_runtime.h>
#include <cuda_bf16.h>
#include <math.h>
#include <stdint.h>

// Problem constants (fixed shapes)
#define NN 8192
#define DD 256
#define NS 32
#define ND_TOT (NN*DD)
#define COEFF_C 0.125f        // d/(n*EPS^2) = 256/(8192*0.25)
#define ETA_C 0.5f
#define LNEPS_C 1e-5f
#define KSPLIT_PHI 16
#define AP_SPLITK 16
#define AP_KCH 512            // k per CTA (two 256-k U halves)
#define KSTEPS 32             // 16-k MMA steps per CTA

// packed-U smem layout strides (bytes) — covers 256 k (16 steps)
#define UT4 8736              // t4-block stride, == 32 mod 128 (bank spread)
#define USS 272               // s-stride: 16 steps x 16B + 16B pad

// A-stage smem layout: [16 k][128 m] fp32, row stride 132 floats (528 B)
#define AROW 528
#define ABUF 8448             // 16 * 528

// ---------------- device scratch (no allocation allowed) ----------------
__device__ float d_Ubuf[NN*128];                 // columns [32k,32k+32) = U_k, U_0 = V
__device__ float d_Upart[AP_SPLITK*NN*32];       // split-K partials (16MB)
__device__ float d_PhiPart[KSPLIT_PHI*128*DD];   // split-K partials for Phi
__device__ float d_Phi[128*DD];                  // Phi[k,s,d] at row 32k+s
__device__ float d_G[NS*DD];                     // fused update matrix

// ---------------- f32x2 packed-FMA helpers (Phi pass) ----------------
__device__ __forceinline__ unsigned long long f2pack(float lo, float hi) {
    unsigned long long r;
    asm("mov.b64 %0, {%1,%2};" : "=l"(r) : "f"(lo), "f"(hi));
    return r;
}
__device__ __forceinline__ void f2unpack(unsigned long long v, float& lo, float& hi) {
    asm("mov.b64 {%0,%1}, %2;" : "=f"(lo), "=f"(hi) : "l"(v));
}
__device__ __forceinline__ unsigned long long f2fma(unsigned long long a,
                                                    unsigned long long b,
                                                    unsigned long long c) {
    unsigned long long d;
    asm("fma.rn.f32x2 %0, %1, %2, %3;" : "=l"(d) : "l"(a), "l"(b), "l"(c));
    return d;
}

// ---------------- smem / cp.async / HMMA helpers ----------------
__device__ __forceinline__ uint32_t smem_u32(const void* p) {
    uint32_t a;
    asm("{ .reg .u64 t; cvta.to.shared.u64 t, %1; cvt.u32.u64 %0, t; }"
        : "=r"(a) : "l"(p));
    return a;
}
#define STS128U(addr, a, b, c, d) \
    asm volatile("st.shared.v4.b32 [%0], {%1,%2,%3,%4};" \
                 :: "r"(addr), "r"(a), "r"(b), "r"(c), "r"(d) : "memory")
#define LDS128U(a, b, c, d, addr) \
    asm volatile("ld.shared.v4.b32 {%0,%1,%2,%3}, [%4];" \
                 : "=r"(a), "=r"(b), "=r"(c), "=r"(d) : "r"(addr))
#define LDS32F(v, addr) \
    asm volatile("ld.shared.f32 %0, [%1];" : "=f"(v) : "r"(addr))

#define CP_ASYNC16(dst, src) \
    asm volatile("cp.async.cg.shared.global [%0], [%1], 16;" \
                 :: "r"(dst), "l"(src) : "memory")
#define CP_COMMIT() asm volatile("cp.async.commit_group;" ::: "memory")
#define CP_WAIT(n)  asm volatile("cp.async.wait_group %0;" :: "n"(n) : "memory")

#define MMA_BF16(c, a0, a1, a2, a3, b0, b1) \
    asm volatile("mma.sync.aligned.m16n8k16.row.col.f32.bf16.bf16.f32 " \
        "{%0,%1,%2,%3}, {%4,%5,%6,%7}, {%8,%9}, {%0,%1,%2,%3};" \
        : "+f"((c)[0]), "+f"((c)[1]), "+f"((c)[2]), "+f"((c)[3]) \
        : "r"(a0), "r"(a1), "r"(a2), "r"(a3), "r"(b0), "r"(b1))

__device__ __forceinline__ uint32_t packbf2(float x, float y) {
    __nv_bfloat162 h = __floats2bfloat162_rn(x, y);   // x -> low, y -> high
    return *reinterpret_cast<uint32_t*>(&h);
}

// split fp32 fragment into bf16 hi/lo packed fragments (a0,a1,a2,a3 order)
__device__ __forceinline__ void cvt_frag(const float* d, uint32_t* ah, uint32_t* al) {
    const int p0[4] = {0, 4, 2, 6};
    #pragma unroll
    for (int r = 0; r < 4; ++r) {
        float x = d[p0[r]], y = d[p0[r] + 1];
        uint32_t hp = packbf2(x, y);
        float xr = x - __uint_as_float(hp << 16);
        float yr = y - __uint_as_float(hp & 0xFFFF0000u);
        ah[r] = hp;
        al[r] = packbf2(xr, yr);
    }
}

// ============================================================================
// HMMA A-pass v8 (2-term bf16 split, 3 MMAs/product, m16/warp, 8 warps,
// cp.async.cg-staged A, single-sync double-buffer rotation):
//   Part[z][m][s] = sum_{k in chunk z} A[k,m] * U[k,s]
// Pipeline per kstep: CP_WAIT(0) -> ONE __syncthreads -> issue next stage
// -> consume. The single barrier proves both data-visibility of the waited
// stage and read-completion of the buffer about to be overwritten.
// ============================================================================
__global__ __launch_bounds__(256, 4) void apass_mma_kernel(
    const float* __restrict__ A,
    const float* __restrict__ U, int ldU,
    float* __restrict__ part)
{
    __shared__ __align__(16) uint8_t sU[4*UT4];    // 34944 B (256 k)
    __shared__ __align__(16) uint8_t sA[2*ABUF];   // 16896 B

    const int tid  = threadIdx.x;
    const int wid  = tid >> 5;
    const int lane = tid & 31;
    const int g    = lane >> 2;
    const int t4   = lane & 3;
    const int m0   = blockIdx.x * 128 + wid * 16;
    const int kz   = blockIdx.y * AP_KCH;
    const uint32_t sUb = smem_u32(sU);
    const uint32_t sAb = smem_u32(sA);

    // ---- A-stage addressing for this thread (2 chunks of 16B per kstep) ----
    const int c0   = tid;
    const int r0c  = c0 >> 5,  q0 = c0 & 31;
    const int r1c  = (c0 + 256) >> 5, q1 = (c0 + 256) & 31;
    const float* gA0 = A + (size_t)(kz + r0c) * NN + blockIdx.x*128 + q0*4;
    const float* gA1 = A + (size_t)(kz + r1c) * NN + blockIdx.x*128 + q1*4;
    const uint32_t dA0 = sAb + (uint32_t)(r0c*AROW + q0*16);
    const uint32_t dA1 = sAb + (uint32_t)(r1c*AROW + q1*16);

    // ---- stage a 256-k U half as packed b-fragment words ----
    #define STAGE_U(kh) do { \
        _Pragma("unroll") \
        for (int it = 0; it < 8; ++it) { \
            int u  = it * 256 + tid; \
            int s  = u & 31; \
            int st_ = (u >> 5) & 15; \
            int tt = u >> 9; \
            int k0 = (kh) + st_*16 + tt*2; \
            float v0 = __ldg(U + (size_t)k0      * ldU + s); \
            float v1 = __ldg(U + (size_t)(k0+1)  * ldU + s); \
            float v2 = __ldg(U + (size_t)(k0+8)  * ldU + s); \
            float v3 = __ldg(U + (size_t)(k0+9)  * ldU + s); \
            uint32_t bh0 = packbf2(v0, v1); \
            uint32_t bl0 = packbf2(v0 - __uint_as_float(bh0 << 16), \
                                   v1 - __uint_as_float(bh0 & 0xFFFF0000u)); \
            uint32_t bh1 = packbf2(v2, v3); \
            uint32_t bl1 = packbf2(v2 - __uint_as_float(bh1 << 16), \
                                   v3 - __uint_as_float(bh1 & 0xFFFF0000u)); \
            uint32_t ad = sUb + tt*UT4 + s*USS + st_*16; \
            STS128U(ad, bh0, bh1, bl0, bl1); \
        } \
    } while (0)

    STAGE_U(kz);

    // ---- accumulators: [nt][4] (m16 per warp) ----
    float c[4][4];
    #pragma unroll
    for (int n = 0; n < 4; ++n)
        #pragma unroll
        for (int i = 0; i < 4; ++i) c[n][i] = 0.f;

    const uint32_t fb = sAb + (uint32_t)(t4*2*AROW + (wid*16 + g)*4);

    // prologue: issue kstep 0 into buffer 0
    CP_ASYNC16(dA0, gA0);
    CP_ASYNC16(dA1, gA1);
    CP_COMMIT();

    #pragma unroll 2
    for (int st = 0; st < KSTEPS; ++st) {
        const uint32_t cb = (st & 1) ? ABUF : 0;

        // stage st has arrived (sole group in flight)
        CP_WAIT(0);
        __syncthreads();   // data visible to all warps; prior reads of the
                           // other buffer (iter st-1) are complete

        if (st == 16) {
            // all half-0 sU reads finished at the barrier above
            STAGE_U(kz + 256);
            __syncthreads();   // new U half visible before consumption
        }

        // issue next stage into the other buffer (safe per the barrier)
        if (st + 1 < KSTEPS) {
            const uint32_t nb = ((st + 1) & 1) ? ABUF : 0;
            const size_t go = (size_t)(st + 1) * 16 * NN;
            CP_ASYNC16(dA0 + nb, gA0 + go);
            CP_ASYNC16(dA1 + nb, gA1 + go);
            CP_COMMIT();
        }

        // load the 8 A-fragment scalars from smem (conflict-free LDS.32)
        float d[8];
        const uint32_t b = fb + cb;
        LDS32F(d[0], b);
        LDS32F(d[1], b + AROW);
        LDS32F(d[2], b + 8*AROW);
        LDS32F(d[3], b + 9*AROW);
        LDS32F(d[4], b + 32);
        LDS32F(d[5], b + AROW + 32);
        LDS32F(d[6], b + 8*AROW + 32);
        LDS32F(d[7], b + 9*AROW + 32);

        uint32_t ah[4], al[4];
        cvt_frag(d, ah, al);

        const uint32_t ub = sUb + t4*UT4 + g*USS + (st & 15)*16;
        #pragma unroll
        for (int nt = 0; nt < 4; ++nt) {
            uint32_t bh0, bh1, bl0, bl1;
            LDS128U(bh0, bh1, bl0, bl1, ub + nt*(8*USS));
            MMA_BF16(c[nt], ah[0],ah[1],ah[2],ah[3], bh0, bh1);
            MMA_BF16(c[nt], ah[0],ah[1],ah[2],ah[3], bl0, bl1);
            MMA_BF16(c[nt], al[0],al[1],al[2],al[3], bh0, bh1);
        }
    }

    // ---- epilogue: C fragment -> Part[z][m][s] ----
    float* pp = part + (size_t)blockIdx.y * (NN*32);
    #pragma unroll
    for (int nt = 0; nt < 4; ++nt) {
        int s = nt*8 + t4*2;
        *(float2*)&pp[(size_t)(m0 + g    )*32 + s] = make_float2(c[nt][0], c[nt][1]);
        *(float2*)&pp[(size_t)(m0 + g + 8)*32 + s] = make_float2(c[nt][2], c[nt][3]);
    }
    #undef STAGE_U
}

// reduce split-K partials (fixed order) into a Ubuf column block (ld=128)
__global__ void reduceU_kernel(float* __restrict__ dst /* Ubuf + colofs */) {
    int i4 = blockIdx.x * blockDim.x + threadIdx.x;   // 65536 float4 slots
    float4 s = make_float4(0.f, 0.f, 0.f, 0.f);
    #pragma unroll
    for (int z = 0; z < AP_SPLITK; ++z) {
        float4 v = *(const float4*)&d_Upart[(size_t)z * (NN*32) + (size_t)i4 * 4];
        s.x += v.x; s.y += v.y; s.z += v.z; s.w += v.w;
    }
    int row = i4 >> 3, c = (i4 & 7) * 4;
    *(float4*)&dst[row*128 + c] = s;
}

// ---------------- generic skinny C = X^T Y kernel (Phi pass) ----------------
template<int MT, int NT, int TJ>
__global__ __launch_bounds__(256) void xty_kernel(
    const float* __restrict__ X, int ldX,
    const float* __restrict__ Y, int ldY,
    float* __restrict__ C, int ldC, int czstride,
    int kchunk)
{
    __shared__ __align__(16) float Xs[TJ*MT];
    __shared__ __align__(16) float Ys[TJ*NT];

    const int tid = threadIdx.x;
    const int m0 = blockIdx.x * MT;
    const int n0 = blockIdx.y * NT;
    const int i_local = tid % MT;
    const int n_base  = (tid / MT) * 8;

    unsigned long long acc0 = 0ull, acc1 = 0ull, acc2 = 0ull, acc3 = 0ull;

    const int ntiles = kchunk / TJ;
    const int kbase = blockIdx.z * kchunk;

    for (int t = 0; t < ntiles; ++t) {
        const int k0 = kbase + t * TJ;
        #pragma unroll
        for (int r = 0; r < (TJ*MT/1024); ++r) {
            int idx = r * 256 + tid;
            int row = idx / (MT/4);
            int c   = idx % (MT/4);
            *(float4*)&Xs[row*MT + c*4] =
                *(const float4*)(X + (size_t)(k0 + row) * ldX + m0 + c*4);
        }
        #pragma unroll
        for (int r = 0; r < (TJ*NT/1024); ++r) {
            int idx = r * 256 + tid;
            int row = idx / (NT/4);
            int c   = idx % (NT/4);
            *(float4*)&Ys[row*NT + c*4] =
                *(const float4*)(Y + (size_t)(k0 + row) * ldY + n0 + c*4);
        }
        __syncthreads();
        #pragma unroll
        for (int j = 0; j < TJ; ++j) {
            float a = Xs[j*MT + i_local];
            unsigned long long a2 = f2pack(a, a);
            const unsigned long long* yp =
                reinterpret_cast<const unsigned long long*>(&Ys[j*NT + n_base]);
            acc0 = f2fma(a2, yp[0], acc0);
            acc1 = f2fma(a2, yp[1], acc1);
            acc2 = f2fma(a2, yp[2], acc2);
            acc3 = f2fma(a2, yp[3], acc3);
        }
        __syncthreads();
    }

    float o[8];
    f2unpack(acc0, o[0], o[1]); f2unpack(acc1, o[2], o[3]);
    f2unpack(acc2, o[4], o[5]); f2unpack(acc3, o[6], o[7]);
    float* cp = C + (size_t)blockIdx.z * czstride
                  + (size_t)(m0 + i_local) * ldC + n0 + n_base;
    *(float4*)cp     = make_float4(o[0], o[1], o[2], o[3]);
    *(float4*)(cp+4) = make_float4(o[4], o[5], o[6], o[7]);
}

// ---------------- copy V into Ubuf columns [0,32) ----------------
__global__ void copyV_kernel(const float* __restrict__ V) {
    int idx = blockIdx.x * blockDim.x + threadIdx.x;   // 65536 float4s
    int i = idx >> 3, c = idx & 7;
    *(float4*)&d_Ubuf[i*128 + c*4] = *(const float4*)(V + i*32 + c*4);
}

// ---------------- reduce split-K Phi partials (fixed order) ----------------
__global__ void reduce_phi_kernel() {
    int i = blockIdx.x * blockDim.x + threadIdx.x;     // 32768 elements
    float s = 0.f;
    #pragma unroll
    for (int z = 0; z < KSPLIT_PHI; ++z) s += d_PhiPart[z * (128*DD) + i];
    d_Phi[i] = s;
}

// ---------------- ncu alignment pads (deterministic, overwritten later) ----
__global__ void pad_kernel(int v) {
    if (threadIdx.x == 0) d_G[v] = 0.f;   // d_G fully rewritten by smallmath
}

// ---- Sherman-Morrison + mixing -> G (32x256), with scalars fused in ----
__global__ void smallmath_kernel(const float* __restrict__ eigvals,
                                 const float* __restrict__ spec_logits,
                                 const float* __restrict__ lap_logits,
                                 const float* __restrict__ hop_weights,
                                 float* __restrict__ out, int out_size)
{
    int s = blockIdx.x;     // 32 blocks
    int d = threadIdx.x;    // 256 threads
    __shared__ float red[256];
    __shared__ float sh_hw[4];
    __shared__ float sh_sw, sh_le;

    if (d < 32) {
        int t = d;
        float sl = spec_logits[t];
        float m = sl;
        #pragma unroll
        for (int o = 16; o; o >>= 1) m = fmaxf(m, __shfl_xor_sync(0xffffffffu, m, o));
        float e = expf(sl - m);
        float ssum = e;
        #pragma unroll
        for (int o = 16; o; o >>= 1) ssum += __shfl_xor_sync(0xffffffffu, ssum, o);
        float sw = e / ssum;
        float x = lap_logits[t];
        float sp = fmaxf(x, 0.f) + log1pf(expf(-fabsf(x)));
        float le = sp * eigvals[t];
        if (t == s) { sh_sw = sw; sh_le = le; }
        float hw = 0.f;
        if (t < 4) {
            float h = hop_weights[t];
            float mh = h;
            #pragma unroll
            for (int o = 2; o; o >>= 1) mh = fmaxf(mh, __shfl_xor_sync(0xFu, mh, o));
            float eh = expf(h - mh);
            float shs = eh;
            #pragma unroll
            for (int o = 2; o; o >>= 1) shs += __shfl_xor_sync(0xFu, shs, o);
            hw = eh / shs;
            sh_hw[t] = hw;
        }
        if (s == 0 && out_size >= ND_TOT + 36) {
            out[ND_TOT + 4 + t] = sw;
            if (t < 4) out[ND_TOT + t] = hw;
        }
    }
    __syncthreads();

    float phv[4], ssk[4];
    #pragma unroll
    for (int k = 0; k < 4; ++k) {
        float p = d_Phi[(k*32 + s)*DD + d];
        phv[k] = p;
        red[d] = p * p;
        __syncthreads();
        #pragma unroll
        for (int o = 128; o > 0; o >>= 1) {
            if (d < o) red[d] += red[d + o];
            __syncthreads();
        }
        ssk[k] = red[0];
        __syncthreads();
    }
    float qs = 0.f, ps = 0.f;
    #pragma unroll
    for (int k = 0; k < 4; ++k) {
        float q = COEFF_C * phv[k] / (1.f + COEFF_C * ssk[k]);
        qs = fmaf(sh_hw[k], q, qs);
        ps = fmaf(sh_hw[k], phv[k], ps);
    }
    d_G[s*DD + d] = ETA_C * (sh_sw * qs - sh_le * ps);
}

// ---------------- fused update + soft-threshold + LayerNorm ----------------
__global__ __launch_bounds__(256) void final_kernel(
    const float* __restrict__ H, const float* __restrict__ V,
    const float* __restrict__ thr, const float* __restrict__ gamma,
    const float* __restrict__ beta, float* __restrict__ out)
{
    int n = blockIdx.x;      // 8192 rows
    int d = threadIdx.x;     // 256
    __shared__ float vs[32];
    __shared__ float rs1[8], rs2[8];
    if (d < 32) vs[d] = V[n*32 + d];
    __syncthreads();

    float acc = H[(size_t)n*DD + d];
    #pragma unroll
    for (int s = 0; s < 32; ++s) acc = fmaf(vs[s], d_G[s*DD + d], acc);

    float ab = fabsf(acc) - thr[d];
    float y = (ab > 0.f) ? copysignf(ab, acc) : 0.f;

    float s1 = y, s2 = y * y;
    #pragma unroll
    for (int o = 16; o; o >>= 1) {
        s1 += __shfl_xor_sync(0xffffffffu, s1, o);
        s2 += __shfl_xor_sync(0xffffffffu, s2, o);
    }
    int w = d >> 5, l = d & 31;
    if (l == 0) { rs1[w] = s1; rs2[w] = s2; }
    __syncthreads();
    if (d == 0) {
        float a = 0.f, b = 0.f;
        #pragma unroll
        for (int i = 0; i < 8; ++i) { a += rs1[i]; b += rs2[i]; }
        rs1[0] = a; rs2[0] = b;
    }
    __syncthreads();
    float mu  = rs1[0] * (1.f/256.f);
    float var = rs2[0] * (1.f/256.f) - mu * mu;
    out[(size_t)n*DD + d] = (y - mu) * rsqrtf(var + LNEPS_C) * gamma[d] + beta[d];
}

// ---------------- launch ----------------
extern "C" void kernel_launch(void* const* d_in, const int* in_sizes, int n_in,
                              void* d_out, int out_size)
{
    const float* H           = (const float*)d_in[0];
    const float* A           = (const float*)d_in[1];
    const float* V           = (const float*)d_in[2];
    const float* eigvals     = (const float*)d_in[3];
    const float* spec_logits = (const float*)d_in[4];
    const float* lap_logits  = (const float*)d_in[5];
    const float* hop_weights = (const float*)d_in[6];
    const float* thr         = (const float*)d_in[7];
    const float* ln_gamma    = (const float*)d_in[8];
    const float* ln_beta     = (const float*)d_in[9];
    float* out = (float*)d_out;

    float* Ubuf = nullptr;
    float* Upart = nullptr;
    float* PhiPart = nullptr;
    cudaGetSymbolAddress((void**)&Ubuf, d_Ubuf);
    cudaGetSymbolAddress((void**)&Upart, d_Upart);
    cudaGetSymbolAddress((void**)&PhiPart, d_PhiPart);

    // idx 0..2 — ncu profiles launch idx 3 (= first apass)
    copyV_kernel<<<256, 256>>>(V);
    pad_kernel<<<1, 32>>>(0);
    pad_kernel<<<1, 32>>>(1);

    // three HMMA passes: U_{k+1} = A^T U_k   (idx 3 = first apass)
    dim3 gA(NN/128, AP_SPLITK);   // (64, 16) = 1024 CTAs
    apass_mma_kernel<<<gA, 256>>>(A, V, 32, Upart);
    reduceU_kernel<<<256, 256>>>(Ubuf + 32);
    apass_mma_kernel<<<gA, 256>>>(A, Ubuf + 32, 128, Upart);
    reduceU_kernel<<<256, 256>>>(Ubuf + 64);
    apass_mma_kernel<<<gA, 256>>>(A, Ubuf + 64, 128, Upart);
    reduceU_kernel<<<256, 256>>>(Ubuf + 96);

    // Phi = Ubuf^T H  (128 x 256), 16-way split-K into partials
    dim3 g3(4, 4, KSPLIT_PHI);
    xty_kernel<32,64,64><<<g3, 256>>>(Ubuf, 128, H, DD, PhiPart, DD, 128*DD, NN/KSPLIT_PHI);
    reduce_phi_kernel<<<128, 256>>>();
    // Sherman-Morrison + scalars + mixing -> G
    smallmath_kernel<<<32, 256>>>(eigvals, spec_logits, lap_logits, hop_weights,
                                  out, out_size);
    // H_out = LN(softthresh(H + V @ G))
    final_kernel<<<NN, 256>>>(H, V, thr, ln_gamma, ln_beta, out);
}

// round 14
// speedup vs baseline: 1.1319x; 1.1319x over previous
#include <cuda_runtime.h>
#include <cuda_bf16.h>
#include <math.h>
#include <stdint.h>

// Problem constants (fixed shapes)
#define NN 8192
#define DD 256
#define NS 32
#define ND_TOT (NN*DD)
#define COEFF_C 0.125f        // d/(n*EPS^2) = 256/(8192*0.25)
#define ETA_C 0.5f
#define LNEPS_C 1e-5f
#define KSPLIT_PHI 16
#define AP_SPLITK 16
#define AP_KCH 512            // k per CTA (four 128-k U quarters)
#define KSTEPS 32             // 16-k MMA steps per CTA

// packed-U smem layout strides (bytes) — covers 128 k (8 steps)
#define USS 144               // s-stride: 8 steps x 16B + 16B pad
#define UT4 4640              // t4-block stride (32*USS=4608, +32 pad; ==32 mod 128)

// A-stage smem layout: [16 k][128 m] fp32, row stride 132 floats (528 B)
#define AROW 528
#define ABUF 8448             // 16 * 528

// ---------------- device scratch (no allocation allowed) ----------------
__device__ float d_Ubuf[NN*128];                 // columns [32k,32k+32) = U_k, U_0 = V
__device__ float d_Upart[AP_SPLITK*NN*32];       // split-K partials (16MB)
__device__ float d_PhiPart[KSPLIT_PHI*128*DD];   // split-K partials for Phi
__device__ float d_Phi[128*DD];                  // Phi[k,s,d] at row 32k+s
__device__ float d_G[NS*DD];                     // fused update matrix

// ---------------- f32x2 packed-FMA helpers (Phi pass) ----------------
__device__ __forceinline__ unsigned long long f2pack(float lo, float hi) {
    unsigned long long r;
    asm("mov.b64 %0, {%1,%2};" : "=l"(r) : "f"(lo), "f"(hi));
    return r;
}
__device__ __forceinline__ void f2unpack(unsigned long long v, float& lo, float& hi) {
    asm("mov.b64 {%0,%1}, %2;" : "=f"(lo), "=f"(hi) : "l"(v));
}
__device__ __forceinline__ unsigned long long f2fma(unsigned long long a,
                                                    unsigned long long b,
                                                    unsigned long long c) {
    unsigned long long d;
    asm("fma.rn.f32x2 %0, %1, %2, %3;" : "=l"(d) : "l"(a), "l"(b), "l"(c));
    return d;
}

// ---------------- smem / cp.async / HMMA helpers ----------------
__device__ __forceinline__ uint32_t smem_u32(const void* p) {
    uint32_t a;
    asm("{ .reg .u64 t; cvta.to.shared.u64 t, %1; cvt.u32.u64 %0, t; }"
        : "=r"(a) : "l"(p));
    return a;
}
#define STS128U(addr, a, b, c, d) \
    asm volatile("st.shared.v4.b32 [%0], {%1,%2,%3,%4};" \
                 :: "r"(addr), "r"(a), "r"(b), "r"(c), "r"(d) : "memory")
#define LDS128U(a, b, c, d, addr) \
    asm volatile("ld.shared.v4.b32 {%0,%1,%2,%3}, [%4];" \
                 : "=r"(a), "=r"(b), "=r"(c), "=r"(d) : "r"(addr))
#define LDS32F(v, addr) \
    asm volatile("ld.shared.f32 %0, [%1];" : "=f"(v) : "r"(addr))

#define CP_ASYNC16(dst, src) \
    asm volatile("cp.async.cg.shared.global [%0], [%1], 16;" \
                 :: "r"(dst), "l"(src) : "memory")
#define CP_COMMIT() asm volatile("cp.async.commit_group;" ::: "memory")
#define CP_WAIT(n)  asm volatile("cp.async.wait_group %0;" :: "n"(n) : "memory")

#define MMA_BF16(c, a0, a1, a2, a3, b0, b1) \
    asm volatile("mma.sync.aligned.m16n8k16.row.col.f32.bf16.bf16.f32 " \
        "{%0,%1,%2,%3}, {%4,%5,%6,%7}, {%8,%9}, {%0,%1,%2,%3};" \
        : "+f"((c)[0]), "+f"((c)[1]), "+f"((c)[2]), "+f"((c)[3]) \
        : "r"(a0), "r"(a1), "r"(a2), "r"(a3), "r"(b0), "r"(b1))

__device__ __forceinline__ uint32_t packbf2(float x, float y) {
    __nv_bfloat162 h = __floats2bfloat162_rn(x, y);   // x -> low, y -> high
    return *reinterpret_cast<uint32_t*>(&h);
}

// split fp32 fragment into bf16 hi/lo packed fragments (a0,a1,a2,a3 order)
__device__ __forceinline__ void cvt_frag(const float* d, uint32_t* ah, uint32_t* al) {
    const int p0[4] = {0, 4, 2, 6};
    #pragma unroll
    for (int r = 0; r < 4; ++r) {
        float x = d[p0[r]], y = d[p0[r] + 1];
        uint32_t hp = packbf2(x, y);
        float xr = x - __uint_as_float(hp << 16);
        float yr = y - __uint_as_float(hp & 0xFFFF0000u);
        ah[r] = hp;
        al[r] = packbf2(xr, yr);
    }
}

// ============================================================================
// HMMA A-pass v9 (2-term bf16 split, 3 MMAs/product, m16/warp, 8 warps,
// 3-stage cp.async.cg A pipeline — TWO groups in flight during waits):
//   Part[z][m][s] = sum_{k in chunk z} A[k,m] * U[k,s]
// R12 schedule (issue-ahead THEN wait) with depth 2 instead of 1.
// U staged in 128-k quarters (8 ksteps) to make smem room for 3 A buffers.
// ============================================================================
__global__ __launch_bounds__(256, 4) void apass_mma_kernel(
    const float* __restrict__ A,
    const float* __restrict__ U, int ldU,
    float* __restrict__ part)
{
    __shared__ __align__(16) uint8_t sU[4*UT4];    // 18560 B (128 k)
    __shared__ __align__(16) uint8_t sA[3*ABUF];   // 25344 B

    const int tid  = threadIdx.x;
    const int wid  = tid >> 5;
    const int lane = tid & 31;
    const int g    = lane >> 2;
    const int t4   = lane & 3;
    const int m0   = blockIdx.x * 128 + wid * 16;
    const int kz   = blockIdx.y * AP_KCH;
    const uint32_t sUb = smem_u32(sU);
    const uint32_t sAb = smem_u32(sA);

    // ---- A-stage addressing for this thread (2 chunks of 16B per kstep) ----
    const int c0   = tid;
    const int r0c  = c0 >> 5,  q0 = c0 & 31;
    const int r1c  = (c0 + 256) >> 5, q1 = (c0 + 256) & 31;
    const float* gA0 = A + (size_t)(kz + r0c) * NN + blockIdx.x*128 + q0*4;
    const float* gA1 = A + (size_t)(kz + r1c) * NN + blockIdx.x*128 + q1*4;
    const uint32_t dA0 = sAb + (uint32_t)(r0c*AROW + q0*16);
    const uint32_t dA1 = sAb + (uint32_t)(r1c*AROW + q1*16);

    // ---- stage a 128-k U quarter (8 ksteps) as packed b-fragment words ----
    #define STAGE_U(kh) do { \
        _Pragma("unroll") \
        for (int it = 0; it < 4; ++it) { \
            int u  = it * 256 + tid;        /* 0..1023 */ \
            int s  = u & 31; \
            int st_ = (u >> 5) & 7; \
            int tt = u >> 8; \
            int k0 = (kh) + st_*16 + tt*2; \
            float v0 = __ldg(U + (size_t)k0      * ldU + s); \
            float v1 = __ldg(U + (size_t)(k0+1)  * ldU + s); \
            float v2 = __ldg(U + (size_t)(k0+8)  * ldU + s); \
            float v3 = __ldg(U + (size_t)(k0+9)  * ldU + s); \
            uint32_t bh0 = packbf2(v0, v1); \
            uint32_t bl0 = packbf2(v0 - __uint_as_float(bh0 << 16), \
                                   v1 - __uint_as_float(bh0 & 0xFFFF0000u)); \
            uint32_t bh1 = packbf2(v2, v3); \
            uint32_t bl1 = packbf2(v2 - __uint_as_float(bh1 << 16), \
                                   v3 - __uint_as_float(bh1 & 0xFFFF0000u)); \
            uint32_t ad = sUb + tt*UT4 + s*USS + st_*16; \
            STS128U(ad, bh0, bh1, bl0, bl1); \
        } \
    } while (0)

    STAGE_U(kz);

    // ---- accumulators: [nt][4] (m16 per warp) ----
    float c[4][4];
    #pragma unroll
    for (int n = 0; n < 4; ++n)
        #pragma unroll
        for (int i = 0; i < 4; ++i) c[n][i] = 0.f;

    const uint32_t fb = sAb + (uint32_t)(t4*2*AROW + (wid*16 + g)*4);

    // prologue: issue ksteps 0 and 1 as separate groups
    CP_ASYNC16(dA0, gA0);
    CP_ASYNC16(dA1, gA1);
    CP_COMMIT();
    CP_ASYNC16(dA0 + ABUF, gA0 + (size_t)16*NN);
    CP_ASYNC16(dA1 + ABUF, gA1 + (size_t)16*NN);
    CP_COMMIT();

    #pragma unroll
    for (int st = 0; st < KSTEPS; ++st) {
        // re-stage U quarter (trailing sync of st-1 protects old reads;
        // the sync below publishes before consumption)
        if (st > 0 && (st & 7) == 0) {
            STAGE_U(kz + st*16);
        }
        const uint32_t cb = (uint32_t)((st % 3) * ABUF);

        // issue two-ahead into buffer (st+2)%3 (its reads finished at the
        // trailing sync of iteration st-1), then wait with 2 in flight
        if (st + 2 < KSTEPS) {
            const uint32_t nb = (uint32_t)(((st + 2) % 3) * ABUF);
            const size_t go = (size_t)(st + 2) * 16 * NN;
            CP_ASYNC16(dA0 + nb, gA0 + go);
            CP_ASYNC16(dA1 + nb, gA1 + go);
            CP_COMMIT();
            CP_WAIT(2);
        } else if (st + 1 < KSTEPS) {
            CP_WAIT(1);
        } else {
            CP_WAIT(0);
        }
        __syncthreads();

        // load the 8 A-fragment scalars from smem (conflict-free LDS.32)
        float d[8];
        const uint32_t b = fb + cb;
        LDS32F(d[0], b);
        LDS32F(d[1], b + AROW);
        LDS32F(d[2], b + 8*AROW);
        LDS32F(d[3], b + 9*AROW);
        LDS32F(d[4], b + 32);
        LDS32F(d[5], b + AROW + 32);
        LDS32F(d[6], b + 8*AROW + 32);
        LDS32F(d[7], b + 9*AROW + 32);

        uint32_t ah[4], al[4];
        cvt_frag(d, ah, al);

        const uint32_t ub = sUb + t4*UT4 + g*USS + (st & 7)*16;
        #pragma unroll
        for (int nt = 0; nt < 4; ++nt) {
            uint32_t bh0, bh1, bl0, bl1;
            LDS128U(bh0, bh1, bl0, bl1, ub + nt*(8*USS));
            MMA_BF16(c[nt], ah[0],ah[1],ah[2],ah[3], bh0, bh1);
            MMA_BF16(c[nt], ah[0],ah[1],ah[2],ah[3], bl0, bl1);
            MMA_BF16(c[nt], al[0],al[1],al[2],al[3], bh0, bh1);
        }
        __syncthreads();   // reads of buffer cb and current sU quarter done
    }

    // ---- epilogue: C fragment -> Part[z][m][s] ----
    float* pp = part + (size_t)blockIdx.y * (NN*32);
    #pragma unroll
    for (int nt = 0; nt < 4; ++nt) {
        int s = nt*8 + t4*2;
        *(float2*)&pp[(size_t)(m0 + g    )*32 + s] = make_float2(c[nt][0], c[nt][1]);
        *(float2*)&pp[(size_t)(m0 + g + 8)*32 + s] = make_float2(c[nt][2], c[nt][3]);
    }
    #undef STAGE_U
}

// reduce split-K partials (fixed order) into a Ubuf column block (ld=128)
__global__ void reduceU_kernel(float* __restrict__ dst /* Ubuf + colofs */) {
    int i4 = blockIdx.x * blockDim.x + threadIdx.x;   // 65536 float4 slots
    float4 s = make_float4(0.f, 0.f, 0.f, 0.f);
    #pragma unroll
    for (int z = 0; z < AP_SPLITK; ++z) {
        float4 v = *(const float4*)&d_Upart[(size_t)z * (NN*32) + (size_t)i4 * 4];
        s.x += v.x; s.y += v.y; s.z += v.z; s.w += v.w;
    }
    int row = i4 >> 3, c = (i4 & 7) * 4;
    *(float4*)&dst[row*128 + c] = s;
}

// ---------------- generic skinny C = X^T Y kernel (Phi pass) ----------------
template<int MT, int NT, int TJ>
__global__ __launch_bounds__(256) void xty_kernel(
    const float* __restrict__ X, int ldX,
    const float* __restrict__ Y, int ldY,
    float* __restrict__ C, int ldC, int czstride,
    int kchunk)
{
    __shared__ __align__(16) float Xs[TJ*MT];
    __shared__ __align__(16) float Ys[TJ*NT];

    const int tid = threadIdx.x;
    const int m0 = blockIdx.x * MT;
    const int n0 = blockIdx.y * NT;
    const int i_local = tid % MT;
    const int n_base  = (tid / MT) * 8;

    unsigned long long acc0 = 0ull, acc1 = 0ull, acc2 = 0ull, acc3 = 0ull;

    const int ntiles = kchunk / TJ;
    const int kbase = blockIdx.z * kchunk;

    for (int t = 0; t < ntiles; ++t) {
        const int k0 = kbase + t * TJ;
        #pragma unroll
        for (int r = 0; r < (TJ*MT/1024); ++r) {
            int idx = r * 256 + tid;
            int row = idx / (MT/4);
            int c   = idx % (MT/4);
            *(float4*)&Xs[row*MT + c*4] =
                *(const float4*)(X + (size_t)(k0 + row) * ldX + m0 + c*4);
        }
        #pragma unroll
        for (int r = 0; r < (TJ*NT/1024); ++r) {
            int idx = r * 256 + tid;
            int row = idx / (NT/4);
            int c   = idx % (NT/4);
            *(float4*)&Ys[row*NT + c*4] =
                *(const float4*)(Y + (size_t)(k0 + row) * ldY + n0 + c*4);
        }
        __syncthreads();
        #pragma unroll
        for (int j = 0; j < TJ; ++j) {
            float a = Xs[j*MT + i_local];
            unsigned long long a2 = f2pack(a, a);
            const unsigned long long* yp =
                reinterpret_cast<const unsigned long long*>(&Ys[j*NT + n_base]);
            acc0 = f2fma(a2, yp[0], acc0);
            acc1 = f2fma(a2, yp[1], acc1);
            acc2 = f2fma(a2, yp[2], acc2);
            acc3 = f2fma(a2, yp[3], acc3);
        }
        __syncthreads();
    }

    float o[8];
    f2unpack(acc0, o[0], o[1]); f2unpack(acc1, o[2], o[3]);
    f2unpack(acc2, o[4], o[5]); f2unpack(acc3, o[6], o[7]);
    float* cp = C + (size_t)blockIdx.z * czstride
                  + (size_t)(m0 + i_local) * ldC + n0 + n_base;
    *(float4*)cp     = make_float4(o[0], o[1], o[2], o[3]);
    *(float4*)(cp+4) = make_float4(o[4], o[5], o[6], o[7]);
}

// ---------------- copy V into Ubuf columns [0,32) ----------------
__global__ void copyV_kernel(const float* __restrict__ V) {
    int idx = blockIdx.x * blockDim.x + threadIdx.x;   // 65536 float4s
    int i = idx >> 3, c = idx & 7;
    *(float4*)&d_Ubuf[i*128 + c*4] = *(const float4*)(V + i*32 + c*4);
}

// ---------------- reduce split-K Phi partials (fixed order) ----------------
__global__ void reduce_phi_kernel() {
    int i = blockIdx.x * blockDim.x + threadIdx.x;     // 32768 elements
    float s = 0.f;
    #pragma unroll
    for (int z = 0; z < KSPLIT_PHI; ++z) s += d_PhiPart[z * (128*DD) + i];
    d_Phi[i] = s;
}

// ---------------- ncu alignment pads (deterministic, overwritten later) ----
__global__ void pad_kernel(int v) {
    if (threadIdx.x == 0) d_G[v] = 0.f;   // d_G fully rewritten by smallmath
}

// ---- Sherman-Morrison + mixing -> G (32x256), with scalars fused in ----
__global__ void smallmath_kernel(const float* __restrict__ eigvals,
                                 const float* __restrict__ spec_logits,
                                 const float* __restrict__ lap_logits,
                                 const float* __restrict__ hop_weights,
                                 float* __restrict__ out, int out_size)
{
    int s = blockIdx.x;     // 32 blocks
    int d = threadIdx.x;    // 256 threads
    __shared__ float red[256];
    __shared__ float sh_hw[4];
    __shared__ float sh_sw, sh_le;

    if (d < 32) {
        int t = d;
        float sl = spec_logits[t];
        float m = sl;
        #pragma unroll
        for (int o = 16; o; o >>= 1) m = fmaxf(m, __shfl_xor_sync(0xffffffffu, m, o));
        float e = expf(sl - m);
        float ssum = e;
        #pragma unroll
        for (int o = 16; o; o >>= 1) ssum += __shfl_xor_sync(0xffffffffu, ssum, o);
        float sw = e / ssum;
        float x = lap_logits[t];
        float sp = fmaxf(x, 0.f) + log1pf(expf(-fabsf(x)));
        float le = sp * eigvals[t];
        if (t == s) { sh_sw = sw; sh_le = le; }
        float hw = 0.f;
        if (t < 4) {
            float h = hop_weights[t];
            float mh = h;
            #pragma unroll
            for (int o = 2; o; o >>= 1) mh = fmaxf(mh, __shfl_xor_sync(0xFu, mh, o));
            float eh = expf(h - mh);
            float shs = eh;
            #pragma unroll
            for (int o = 2; o; o >>= 1) shs += __shfl_xor_sync(0xFu, shs, o);
            hw = eh / shs;
            sh_hw[t] = hw;
        }
        if (s == 0 && out_size >= ND_TOT + 36) {
            out[ND_TOT + 4 + t] = sw;
            if (t < 4) out[ND_TOT + t] = hw;
        }
    }
    __syncthreads();

    float phv[4], ssk[4];
    #pragma unroll
    for (int k = 0; k < 4; ++k) {
        float p = d_Phi[(k*32 + s)*DD + d];
        phv[k] = p;
        red[d] = p * p;
        __syncthreads();
        #pragma unroll
        for (int o = 128; o > 0; o >>= 1) {
            if (d < o) red[d] += red[d + o];
            __syncthreads();
        }
        ssk[k] = red[0];
        __syncthreads();
    }
    float qs = 0.f, ps = 0.f;
    #pragma unroll
    for (int k = 0; k < 4; ++k) {
        float q = COEFF_C * phv[k] / (1.f + COEFF_C * ssk[k]);
        qs = fmaf(sh_hw[k], q, qs);
        ps = fmaf(sh_hw[k], phv[k], ps);
    }
    d_G[s*DD + d] = ETA_C * (sh_sw * qs - sh_le * ps);
}

// ---------------- fused update + soft-threshold + LayerNorm ----------------
__global__ __launch_bounds__(256) void final_kernel(
    const float* __restrict__ H, const float* __restrict__ V,
    const float* __restrict__ thr, const float* __restrict__ gamma,
    const float* __restrict__ beta, float* __restrict__ out)
{
    int n = blockIdx.x;      // 8192 rows
    int d = threadIdx.x;     // 256
    __shared__ float vs[32];
    __shared__ float rs1[8], rs2[8];
    if (d < 32) vs[d] = V[n*32 + d];
    __syncthreads();

    float acc = H[(size_t)n*DD + d];
    #pragma unroll
    for (int s = 0; s < 32; ++s) acc = fmaf(vs[s], d_G[s*DD + d], acc);

    float ab = fabsf(acc) - thr[d];
    float y = (ab > 0.f) ? copysignf(ab, acc) : 0.f;

    float s1 = y, s2 = y * y;
    #pragma unroll
    for (int o = 16; o; o >>= 1) {
        s1 += __shfl_xor_sync(0xffffffffu, s1, o);
        s2 += __shfl_xor_sync(0xffffffffu, s2, o);
    }
    int w = d >> 5, l = d & 31;
    if (l == 0) { rs1[w] = s1; rs2[w] = s2; }
    __syncthreads();
    if (d == 0) {
        float a = 0.f, b = 0.f;
        #pragma unroll
        for (int i = 0; i < 8; ++i) { a += rs1[i]; b += rs2[i]; }
        rs1[0] = a; rs2[0] = b;
    }
    __syncthreads();
    float mu  = rs1[0] * (1.f/256.f);
    float var = rs2[0] * (1.f/256.f) - mu * mu;
    out[(size_t)n*DD + d] = (y - mu) * rsqrtf(var + LNEPS_C) * gamma[d] + beta[d];
}

// ---------------- launch ----------------
extern "C" void kernel_launch(void* const* d_in, const int* in_sizes, int n_in,
                              void* d_out, int out_size)
{
    const float* H           = (const float*)d_in[0];
    const float* A           = (const float*)d_in[1];
    const float* V           = (const float*)d_in[2];
    const float* eigvals     = (const float*)d_in[3];
    const float* spec_logits = (const float*)d_in[4];
    const float* lap_logits  = (const float*)d_in[5];
    const float* hop_weights = (const float*)d_in[6];
    const float* thr         = (const float*)d_in[7];
    const float* ln_gamma    = (const float*)d_in[8];
    const float* ln_beta     = (const float*)d_in[9];
    float* out = (float*)d_out;

    float* Ubuf = nullptr;
    float* Upart = nullptr;
    float* PhiPart = nullptr;
    cudaGetSymbolAddress((void**)&Ubuf, d_Ubuf);
    cudaGetSymbolAddress((void**)&Upart, d_Upart);
    cudaGetSymbolAddress((void**)&PhiPart, d_PhiPart);

    // idx 0..2 — ncu profiles launch idx 3 (= first apass)
    copyV_kernel<<<256, 256>>>(V);
    pad_kernel<<<1, 32>>>(0);
    pad_kernel<<<1, 32>>>(1);

    // three HMMA passes: U_{k+1} = A^T U_k   (idx 3 = first apass)
    dim3 gA(NN/128, AP_SPLITK);   // (64, 16) = 1024 CTAs
    apass_mma_kernel<<<gA, 256>>>(A, V, 32, Upart);
    reduceU_kernel<<<256, 256>>>(Ubuf + 32);
    apass_mma_kernel<<<gA, 256>>>(A, Ubuf + 32, 128, Upart);
    reduceU_kernel<<<256, 256>>>(Ubuf + 64);
    apass_mma_kernel<<<gA, 256>>>(A, Ubuf + 64, 128, Upart);
    reduceU_kernel<<<256, 256>>>(Ubuf + 96);

    // Phi = Ubuf^T H  (128 x 256), 16-way split-K into partials
    dim3 g3(4, 4, KSPLIT_PHI);
    xty_kernel<32,64,64><<<g3, 256>>>(Ubuf, 128, H, DD, PhiPart, DD, 128*DD, NN/KSPLIT_PHI);
    reduce_phi_kernel<<<128, 256>>>();
    // Sherman-Morrison + scalars + mixing -> G
    smallmath_kernel<<<32, 256>>>(eigvals, spec_logits, lap_logits, hop_weights,
                                  out, out_size);
    // H_out = LN(softthresh(H + V @ G))
    final_kernel<<<NN, 256>>>(H, V, thr, ln_gamma, ln_beta, out);
}

// round 15
// speedup vs baseline: 1.1560x; 1.0213x over previous
#include <cuda_runtime.h>
#include <cuda_bf16.h>
#include <math.h>
#include <stdint.h>

// Problem constants (fixed shapes)
#define NN 8192
#define DD 256
#define NS 32
#define ND_TOT (NN*DD)
#define COEFF_C 0.125f        // d/(n*EPS^2) = 256/(8192*0.25)
#define ETA_C 0.5f
#define LNEPS_C 1e-5f
#define KSPLIT_PHI 16
#define AP_SPLITK 16
#define AP_KCH 512            // k per CTA (four 128-k U quarters)
#define KSTEPS 32             // 16-k MMA steps per CTA

// packed-U smem layout strides (bytes) — covers 128 k (8 steps)
#define USS 144               // s-stride: 8 steps x 16B + 16B pad
#define UT4 4640              // t4-block stride (32*USS=4608, +32 pad; ==32 mod 128)

// A-stage smem layout: [16 k][128 m] fp32, row stride 132 floats (528 B)
#define AROW 528
#define ABUF 8448             // 16 * 528

// ---------------- device scratch (no allocation allowed) ----------------
__device__ float d_Ubuf[NN*128];                 // columns [32k,32k+32) = U_k, U_0 = V
__device__ float d_Upart[AP_SPLITK*NN*32];       // split-K partials (16MB)
__device__ float d_PhiPart[KSPLIT_PHI*128*DD];   // split-K partials for Phi
__device__ float d_G[NS*DD];                     // fused update matrix

// ---------------- f32x2 packed-FMA helpers (Phi pass) ----------------
__device__ __forceinline__ unsigned long long f2pack(float lo, float hi) {
    unsigned long long r;
    asm("mov.b64 %0, {%1,%2};" : "=l"(r) : "f"(lo), "f"(hi));
    return r;
}
__device__ __forceinline__ void f2unpack(unsigned long long v, float& lo, float& hi) {
    asm("mov.b64 {%0,%1}, %2;" : "=f"(lo), "=f"(hi) : "l"(v));
}
__device__ __forceinline__ unsigned long long f2fma(unsigned long long a,
                                                    unsigned long long b,
                                                    unsigned long long c) {
    unsigned long long d;
    asm("fma.rn.f32x2 %0, %1, %2, %3;" : "=l"(d) : "l"(a), "l"(b), "l"(c));
    return d;
}

// ---------------- smem / cp.async / HMMA helpers ----------------
__device__ __forceinline__ uint32_t smem_u32(const void* p) {
    uint32_t a;
    asm("{ .reg .u64 t; cvta.to.shared.u64 t, %1; cvt.u32.u64 %0, t; }"
        : "=r"(a) : "l"(p));
    return a;
}
#define STS128U(addr, a, b, c, d) \
    asm volatile("st.shared.v4.b32 [%0], {%1,%2,%3,%4};" \
                 :: "r"(addr), "r"(a), "r"(b), "r"(c), "r"(d) : "memory")
#define LDS128U(a, b, c, d, addr) \
    asm volatile("ld.shared.v4.b32 {%0,%1,%2,%3}, [%4];" \
                 : "=r"(a), "=r"(b), "=r"(c), "=r"(d) : "r"(addr))
#define LDS32F(v, addr) \
    asm volatile("ld.shared.f32 %0, [%1];" : "=f"(v) : "r"(addr))

#define CP_ASYNC16(dst, src) \
    asm volatile("cp.async.cg.shared.global [%0], [%1], 16;" \
                 :: "r"(dst), "l"(src) : "memory")
#define CP_COMMIT() asm volatile("cp.async.commit_group;" ::: "memory")
#define CP_WAIT(n)  asm volatile("cp.async.wait_group %0;" :: "n"(n) : "memory")

#define MMA_BF16(c, a0, a1, a2, a3, b0, b1) \
    asm volatile("mma.sync.aligned.m16n8k16.row.col.f32.bf16.bf16.f32 " \
        "{%0,%1,%2,%3}, {%4,%5,%6,%7}, {%8,%9}, {%0,%1,%2,%3};" \
        : "+f"((c)[0]), "+f"((c)[1]), "+f"((c)[2]), "+f"((c)[3]) \
        : "r"(a0), "r"(a1), "r"(a2), "r"(a3), "r"(b0), "r"(b1))

__device__ __forceinline__ uint32_t packbf2(float x, float y) {
    __nv_bfloat162 h = __floats2bfloat162_rn(x, y);   // x -> low, y -> high
    return *reinterpret_cast<uint32_t*>(&h);
}

// split fp32 fragment into bf16 hi/lo packed fragments (a0,a1,a2,a3 order)
__device__ __forceinline__ void cvt_frag(const float* d, uint32_t* ah, uint32_t* al) {
    const int p0[4] = {0, 4, 2, 6};
    #pragma unroll
    for (int r = 0; r < 4; ++r) {
        float x = d[p0[r]], y = d[p0[r] + 1];
        uint32_t hp = packbf2(x, y);
        float xr = x - __uint_as_float(hp << 16);
        float yr = y - __uint_as_float(hp & 0xFFFF0000u);
        ah[r] = hp;
        al[r] = packbf2(xr, yr);
    }
}

// ============================================================================
// HMMA A-pass v10 (2-term bf16 split, 3 MMAs/product, m16/warp, 8 warps,
// 4-stage cp.async.cg A pipeline, ONE __syncthreads per kstep,
// depth-2 issue-ahead):   Part[z][m][s] = sum_{k in chunk z} A[k,m] * U[k,s]
// Safety: buffer (st+2)%4 issued at iter st was last read at iter st-2;
// every warp passing the iter st-1 barrier has finished that read.
// ============================================================================
__global__ __launch_bounds__(256, 4) void apass_mma_kernel(
    const float* __restrict__ A,
    const float* __restrict__ U, int ldU,
    float* __restrict__ part)
{
    __shared__ __align__(16) uint8_t sU[4*UT4];    // 18560 B (128 k)
    __shared__ __align__(16) uint8_t sA[4*ABUF];   // 33792 B

    const int tid  = threadIdx.x;
    const int wid  = tid >> 5;
    const int lane = tid & 31;
    const int g    = lane >> 2;
    const int t4   = lane & 3;
    const int m0   = blockIdx.x * 128 + wid * 16;
    const int kz   = blockIdx.y * AP_KCH;
    const uint32_t sUb = smem_u32(sU);
    const uint32_t sAb = smem_u32(sA);

    // ---- A-stage addressing for this thread (2 chunks of 16B per kstep) ----
    const int c0   = tid;
    const int r0c  = c0 >> 5,  q0 = c0 & 31;
    const int r1c  = (c0 + 256) >> 5, q1 = (c0 + 256) & 31;
    const float* gA0 = A + (size_t)(kz + r0c) * NN + blockIdx.x*128 + q0*4;
    const float* gA1 = A + (size_t)(kz + r1c) * NN + blockIdx.x*128 + q1*4;
    const uint32_t dA0 = sAb + (uint32_t)(r0c*AROW + q0*16);
    const uint32_t dA1 = sAb + (uint32_t)(r1c*AROW + q1*16);

    // ---- stage a 128-k U quarter (8 ksteps) as packed b-fragment words ----
    #define STAGE_U(kh) do { \
        _Pragma("unroll") \
        for (int it = 0; it < 4; ++it) { \
            int u  = it * 256 + tid;        /* 0..1023 */ \
            int s  = u & 31; \
            int st_ = (u >> 5) & 7; \
            int tt = u >> 8; \
            int k0 = (kh) + st_*16 + tt*2; \
            float v0 = __ldg(U + (size_t)k0      * ldU + s); \
            float v1 = __ldg(U + (size_t)(k0+1)  * ldU + s); \
            float v2 = __ldg(U + (size_t)(k0+8)  * ldU + s); \
            float v3 = __ldg(U + (size_t)(k0+9)  * ldU + s); \
            uint32_t bh0 = packbf2(v0, v1); \
            uint32_t bl0 = packbf2(v0 - __uint_as_float(bh0 << 16), \
                                   v1 - __uint_as_float(bh0 & 0xFFFF0000u)); \
            uint32_t bh1 = packbf2(v2, v3); \
            uint32_t bl1 = packbf2(v2 - __uint_as_float(bh1 << 16), \
                                   v3 - __uint_as_float(bh1 & 0xFFFF0000u)); \
            uint32_t ad = sUb + tt*UT4 + s*USS + st_*16; \
            STS128U(ad, bh0, bh1, bl0, bl1); \
        } \
    } while (0)

    STAGE_U(kz);

    // ---- accumulators: [nt][4] (m16 per warp) ----
    float c[4][4];
    #pragma unroll
    for (int n = 0; n < 4; ++n)
        #pragma unroll
        for (int i = 0; i < 4; ++i) c[n][i] = 0.f;

    const uint32_t fb = sAb + (uint32_t)(t4*2*AROW + (wid*16 + g)*4);

    // prologue: issue ksteps 0 and 1 as separate groups
    CP_ASYNC16(dA0, gA0);
    CP_ASYNC16(dA1, gA1);
    CP_COMMIT();
    CP_ASYNC16(dA0 + ABUF, gA0 + (size_t)16*NN);
    CP_ASYNC16(dA1 + ABUF, gA1 + (size_t)16*NN);
    CP_COMMIT();

    #pragma unroll
    for (int st = 0; st < KSTEPS; ++st) {
        // U quarter boundary: barrier so no warp still reads the old quarter,
        // then restage (published by the main barrier below)
        if (st > 0 && (st & 7) == 0) {
            __syncthreads();
            STAGE_U(kz + st*16);
        }

        // issue two-ahead into buffer (st+2)%4, then wait with 2 in flight
        if (st + 2 < KSTEPS) {
            const uint32_t nb = (uint32_t)(((st + 2) & 3) * ABUF);
            const size_t go = (size_t)(st + 2) * 16 * NN;
            CP_ASYNC16(dA0 + nb, gA0 + go);
            CP_ASYNC16(dA1 + nb, gA1 + go);
            CP_COMMIT();
            CP_WAIT(2);
        } else if (st + 1 < KSTEPS) {
            CP_WAIT(1);
        } else {
            CP_WAIT(0);
        }
        __syncthreads();   // the single per-kstep barrier

        // load the 8 A-fragment scalars from smem (conflict-free LDS.32)
        float d[8];
        const uint32_t b = fb + (uint32_t)((st & 3) * ABUF);
        LDS32F(d[0], b);
        LDS32F(d[1], b + AROW);
        LDS32F(d[2], b + 8*AROW);
        LDS32F(d[3], b + 9*AROW);
        LDS32F(d[4], b + 32);
        LDS32F(d[5], b + AROW + 32);
        LDS32F(d[6], b + 8*AROW + 32);
        LDS32F(d[7], b + 9*AROW + 32);

        uint32_t ah[4], al[4];
        cvt_frag(d, ah, al);

        const uint32_t ub = sUb + t4*UT4 + g*USS + (st & 7)*16;
        #pragma unroll
        for (int nt = 0; nt < 4; ++nt) {
            uint32_t bh0, bh1, bl0, bl1;
            LDS128U(bh0, bh1, bl0, bl1, ub + nt*(8*USS));
            MMA_BF16(c[nt], ah[0],ah[1],ah[2],ah[3], bh0, bh1);
            MMA_BF16(c[nt], ah[0],ah[1],ah[2],ah[3], bl0, bl1);
            MMA_BF16(c[nt], al[0],al[1],al[2],al[3], bh0, bh1);
        }
    }

    // ---- epilogue: C fragment -> Part[z][m][s] ----
    float* pp = part + (size_t)blockIdx.y * (NN*32);
    #pragma unroll
    for (int nt = 0; nt < 4; ++nt) {
        int s = nt*8 + t4*2;
        *(float2*)&pp[(size_t)(m0 + g    )*32 + s] = make_float2(c[nt][0], c[nt][1]);
        *(float2*)&pp[(size_t)(m0 + g + 8)*32 + s] = make_float2(c[nt][2], c[nt][3]);
    }
    #undef STAGE_U
}

// reduce split-K partials (fixed order) into a Ubuf column block (ld=128)
__global__ void reduceU_kernel(float* __restrict__ dst /* Ubuf + colofs */) {
    int i4 = blockIdx.x * blockDim.x + threadIdx.x;   // 65536 float4 slots
    float4 s = make_float4(0.f, 0.f, 0.f, 0.f);
    #pragma unroll
    for (int z = 0; z < AP_SPLITK; ++z) {
        float4 v = *(const float4*)&d_Upart[(size_t)z * (NN*32) + (size_t)i4 * 4];
        s.x += v.x; s.y += v.y; s.z += v.z; s.w += v.w;
    }
    int row = i4 >> 3, c = (i4 & 7) * 4;
    *(float4*)&dst[row*128 + c] = s;
}

// ---------------- generic skinny C = X^T Y kernel (Phi pass) ----------------
template<int MT, int NT, int TJ>
__global__ __launch_bounds__(256) void xty_kernel(
    const float* __restrict__ X, int ldX,
    const float* __restrict__ Y, int ldY,
    float* __restrict__ C, int ldC, int czstride,
    int kchunk)
{
    __shared__ __align__(16) float Xs[TJ*MT];
    __shared__ __align__(16) float Ys[TJ*NT];

    const int tid = threadIdx.x;
    const int m0 = blockIdx.x * MT;
    const int n0 = blockIdx.y * NT;
    const int i_local = tid % MT;
    const int n_base  = (tid / MT) * 8;

    unsigned long long acc0 = 0ull, acc1 = 0ull, acc2 = 0ull, acc3 = 0ull;

    const int ntiles = kchunk / TJ;
    const int kbase = blockIdx.z * kchunk;

    for (int t = 0; t < ntiles; ++t) {
        const int k0 = kbase + t * TJ;
        #pragma unroll
        for (int r = 0; r < (TJ*MT/1024); ++r) {
            int idx = r * 256 + tid;
            int row = idx / (MT/4);
            int c   = idx % (MT/4);
            *(float4*)&Xs[row*MT + c*4] =
                *(const float4*)(X + (size_t)(k0 + row) * ldX + m0 + c*4);
        }
        #pragma unroll
        for (int r = 0; r < (TJ*NT/1024); ++r) {
            int idx = r * 256 + tid;
            int row = idx / (NT/4);
            int c   = idx % (NT/4);
            *(float4*)&Ys[row*NT + c*4] =
                *(const float4*)(Y + (size_t)(k0 + row) * ldY + n0 + c*4);
        }
        __syncthreads();
        #pragma unroll
        for (int j = 0; j < TJ; ++j) {
            float a = Xs[j*MT + i_local];
            unsigned long long a2 = f2pack(a, a);
            const unsigned long long* yp =
                reinterpret_cast<const unsigned long long*>(&Ys[j*NT + n_base]);
            acc0 = f2fma(a2, yp[0], acc0);
            acc1 = f2fma(a2, yp[1], acc1);
            acc2 = f2fma(a2, yp[2], acc2);
            acc3 = f2fma(a2, yp[3], acc3);
        }
        __syncthreads();
    }

    float o[8];
    f2unpack(acc0, o[0], o[1]); f2unpack(acc1, o[2], o[3]);
    f2unpack(acc2, o[4], o[5]); f2unpack(acc3, o[6], o[7]);
    float* cp = C + (size_t)blockIdx.z * czstride
                  + (size_t)(m0 + i_local) * ldC + n0 + n_base;
    *(float4*)cp     = make_float4(o[0], o[1], o[2], o[3]);
    *(float4*)(cp+4) = make_float4(o[4], o[5], o[6], o[7]);
}

// ---------------- copy V into Ubuf columns [0,32) ----------------
__global__ void copyV_kernel(const float* __restrict__ V) {
    int idx = blockIdx.x * blockDim.x + threadIdx.x;   // 65536 float4s
    int i = idx >> 3, c = idx & 7;
    *(float4*)&d_Ubuf[i*128 + c*4] = *(const float4*)(V + i*32 + c*4);
}

// ---- Sherman-Morrison + mixing -> G (32x256); scalars + Phi-reduce fused ----
__global__ void smallmath_kernel(const float* __restrict__ eigvals,
                                 const float* __restrict__ spec_logits,
                                 const float* __restrict__ lap_logits,
                                 const float* __restrict__ hop_weights,
                                 float* __restrict__ out, int out_size)
{
    int s = blockIdx.x;     // 32 blocks
    int d = threadIdx.x;    // 256 threads
    __shared__ float red[256];
    __shared__ float sh_hw[4];
    __shared__ float sh_sw, sh_le;

    if (d < 32) {
        int t = d;
        float sl = spec_logits[t];
        float m = sl;
        #pragma unroll
        for (int o = 16; o; o >>= 1) m = fmaxf(m, __shfl_xor_sync(0xffffffffu, m, o));
        float e = expf(sl - m);
        float ssum = e;
        #pragma unroll
        for (int o = 16; o; o >>= 1) ssum += __shfl_xor_sync(0xffffffffu, ssum, o);
        float sw = e / ssum;
        float x = lap_logits[t];
        float sp = fmaxf(x, 0.f) + log1pf(expf(-fabsf(x)));
        float le = sp * eigvals[t];
        if (t == s) { sh_sw = sw; sh_le = le; }
        float hw = 0.f;
        if (t < 4) {
            float h = hop_weights[t];
            float mh = h;
            #pragma unroll
            for (int o = 2; o; o >>= 1) mh = fmaxf(mh, __shfl_xor_sync(0xFu, mh, o));
            float eh = expf(h - mh);
            float shs = eh;
            #pragma unroll
            for (int o = 2; o; o >>= 1) shs += __shfl_xor_sync(0xFu, shs, o);
            hw = eh / shs;
            sh_hw[t] = hw;
        }
        if (s == 0 && out_size >= ND_TOT + 36) {
            out[ND_TOT + 4 + t] = sw;
            if (t < 4) out[ND_TOT + t] = hw;
        }
    }
    __syncthreads();

    float phv[4], ssk[4];
    #pragma unroll
    for (int k = 0; k < 4; ++k) {
        // fused Phi split-K reduction (fixed order)
        float p = 0.f;
        #pragma unroll
        for (int z = 0; z < KSPLIT_PHI; ++z)
            p += d_PhiPart[z*(128*DD) + (k*32 + s)*DD + d];
        phv[k] = p;
        red[d] = p * p;
        __syncthreads();
        #pragma unroll
        for (int o = 128; o > 0; o >>= 1) {
            if (d < o) red[d] += red[d + o];
            __syncthreads();
        }
        ssk[k] = red[0];
        __syncthreads();
    }
    float qs = 0.f, ps = 0.f;
    #pragma unroll
    for (int k = 0; k < 4; ++k) {
        float q = COEFF_C * phv[k] / (1.f + COEFF_C * ssk[k]);
        qs = fmaf(sh_hw[k], q, qs);
        ps = fmaf(sh_hw[k], phv[k], ps);
    }
    d_G[s*DD + d] = ETA_C * (sh_sw * qs - sh_le * ps);
}

// ---------------- fused update + soft-threshold + LayerNorm ----------------
__global__ __launch_bounds__(256) void final_kernel(
    const float* __restrict__ H, const float* __restrict__ V,
    const float* __restrict__ thr, const float* __restrict__ gamma,
    const float* __restrict__ beta, float* __restrict__ out)
{
    int n = blockIdx.x;      // 8192 rows
    int d = threadIdx.x;     // 256
    __shared__ float vs[32];
    __shared__ float rs1[8], rs2[8];
    if (d < 32) vs[d] = V[n*32 + d];
    __syncthreads();

    float acc = H[(size_t)n*DD + d];
    #pragma unroll
    for (int s = 0; s < 32; ++s) acc = fmaf(vs[s], d_G[s*DD + d], acc);

    float ab = fabsf(acc) - thr[d];
    float y = (ab > 0.f) ? copysignf(ab, acc) : 0.f;

    float s1 = y, s2 = y * y;
    #pragma unroll
    for (int o = 16; o; o >>= 1) {
        s1 += __shfl_xor_sync(0xffffffffu, s1, o);
        s2 += __shfl_xor_sync(0xffffffffu, s2, o);
    }
    int w = d >> 5, l = d & 31;
    if (l == 0) { rs1[w] = s1; rs2[w] = s2; }
    __syncthreads();
    if (d == 0) {
        float a = 0.f, b = 0.f;
        #pragma unroll
        for (int i = 0; i < 8; ++i) { a += rs1[i]; b += rs2[i]; }
        rs1[0] = a; rs2[0] = b;
    }
    __syncthreads();
    float mu  = rs1[0] * (1.f/256.f);
    float var = rs2[0] * (1.f/256.f) - mu * mu;
    out[(size_t)n*DD + d] = (y - mu) * rsqrtf(var + LNEPS_C) * gamma[d] + beta[d];
}

// ---------------- launch ----------------
extern "C" void kernel_launch(void* const* d_in, const int* in_sizes, int n_in,
                              void* d_out, int out_size)
{
    const float* H           = (const float*)d_in[0];
    const float* A           = (const float*)d_in[1];
    const float* V           = (const float*)d_in[2];
    const float* eigvals     = (const float*)d_in[3];
    const float* spec_logits = (const float*)d_in[4];
    const float* lap_logits  = (const float*)d_in[5];
    const float* hop_weights = (const float*)d_in[6];
    const float* thr         = (const float*)d_in[7];
    const float* ln_gamma    = (const float*)d_in[8];
    const float* ln_beta     = (const float*)d_in[9];
    float* out = (float*)d_out;

    float* Ubuf = nullptr;
    float* Upart = nullptr;
    float* PhiPart = nullptr;
    cudaGetSymbolAddress((void**)&Ubuf, d_Ubuf);
    cudaGetSymbolAddress((void**)&Upart, d_Upart);
    cudaGetSymbolAddress((void**)&PhiPart, d_PhiPart);

    // U_0 = V into Ubuf (needed only by the Phi pass)
    copyV_kernel<<<256, 256>>>(V);

    // three HMMA passes: U_{k+1} = A^T U_k
    dim3 gA(NN/128, AP_SPLITK);   // (64, 16) = 1024 CTAs
    apass_mma_kernel<<<gA, 256>>>(A, V, 32, Upart);
    reduceU_kernel<<<256, 256>>>(Ubuf + 32);
    apass_mma_kernel<<<gA, 256>>>(A, Ubuf + 32, 128, Upart);
    reduceU_kernel<<<256, 256>>>(Ubuf + 64);
    apass_mma_kernel<<<gA, 256>>>(A, Ubuf + 64, 128, Upart);
    reduceU_kernel<<<256, 256>>>(Ubuf + 96);

    // Phi = Ubuf^T H  (128 x 256), 16-way split-K into partials
    dim3 g3(4, 4, KSPLIT_PHI);
    xty_kernel<32,64,64><<<g3, 256>>>(Ubuf, 128, H, DD, PhiPart, DD, 128*DD, NN/KSPLIT_PHI);
    // Sherman-Morrison + scalars + fused Phi-reduce + mixing -> G
    smallmath_kernel<<<32, 256>>>(eigvals, spec_logits, lap_logits, hop_weights,
                                  out, out_size);
    // H_out = LN(softthresh(H + V @ G))
    final_kernel<<<NN, 256>>>(H, V, thr, ln_gamma, ln_beta, out);
}

// round 16
// speedup vs baseline: 1.2060x; 1.0433x over previous
#include <cuda_runtime.h>
#include <cuda_bf16.h>
#include <math.h>
#include <stdint.h>

// Problem constants (fixed shapes)
#define NN 8192
#define DD 256
#define NS 32
#define ND_TOT (NN*DD)
#define COEFF_C 0.125f        // d/(n*EPS^2) = 256/(8192*0.25)
#define ETA_C 0.5f
#define LNEPS_C 1e-5f
#define KSPLIT_PHI 16
#define AP_SPLITK 8
#define AP_KCH 1024           // k per CTA (eight 128-k U quarters)
#define KSTEPS 64             // 16-k MMA steps per CTA

// packed-U smem layout strides (bytes) — covers 128 k (8 steps)
#define USS 144               // s-stride: 8 steps x 16B + 16B pad
#define UT4 4640              // t4-block stride (32*USS=4608, +32 pad; ==32 mod 128)

// A-stage smem layout: [16 k][128 m] fp32, row stride 132 floats (528 B)
#define AROW 528
#define ABUF 8448             // 16 * 528

// ---------------- device scratch (no allocation allowed) ----------------
__device__ float d_Ubuf[NN*128];                 // columns [32k,32k+32) = U_k, U_0 = V
__device__ float d_Upart[AP_SPLITK*NN*32];       // split-K partials (8MB)
__device__ float d_PhiPart[KSPLIT_PHI*128*DD];   // split-K partials for Phi
__device__ float d_G[NS*DD];                     // fused update matrix

// ---------------- f32x2 packed-FMA helpers (Phi pass) ----------------
__device__ __forceinline__ unsigned long long f2pack(float lo, float hi) {
    unsigned long long r;
    asm("mov.b64 %0, {%1,%2};" : "=l"(r) : "f"(lo), "f"(hi));
    return r;
}
__device__ __forceinline__ void f2unpack(unsigned long long v, float& lo, float& hi) {
    asm("mov.b64 {%0,%1}, %2;" : "=f"(lo), "=f"(hi) : "l"(v));
}
__device__ __forceinline__ unsigned long long f2fma(unsigned long long a,
                                                    unsigned long long b,
                                                    unsigned long long c) {
    unsigned long long d;
    asm("fma.rn.f32x2 %0, %1, %2, %3;" : "=l"(d) : "l"(a), "l"(b), "l"(c));
    return d;
}

// ---------------- smem / cp.async / HMMA helpers ----------------
__device__ __forceinline__ uint32_t smem_u32(const void* p) {
    uint32_t a;
    asm("{ .reg .u64 t; cvta.to.shared.u64 t, %1; cvt.u32.u64 %0, t; }"
        : "=r"(a) : "l"(p));
    return a;
}
#define STS128U(addr, a, b, c, d) \
    asm volatile("st.shared.v4.b32 [%0], {%1,%2,%3,%4};" \
                 :: "r"(addr), "r"(a), "r"(b), "r"(c), "r"(d) : "memory")
#define LDS128U(a, b, c, d, addr) \
    asm volatile("ld.shared.v4.b32 {%0,%1,%2,%3}, [%4];" \
                 : "=r"(a), "=r"(b), "=r"(c), "=r"(d) : "r"(addr))
#define LDS32F(v, addr) \
    asm volatile("ld.shared.f32 %0, [%1];" : "=f"(v) : "r"(addr))

#define CP_ASYNC16(dst, src) \
    asm volatile("cp.async.cg.shared.global [%0], [%1], 16;" \
                 :: "r"(dst), "l"(src) : "memory")
#define CP_COMMIT() asm volatile("cp.async.commit_group;" ::: "memory")
#define CP_WAIT(n)  asm volatile("cp.async.wait_group %0;" :: "n"(n) : "memory")

#define MMA_BF16(c, a0, a1, a2, a3, b0, b1) \
    asm volatile("mma.sync.aligned.m16n8k16.row.col.f32.bf16.bf16.f32 " \
        "{%0,%1,%2,%3}, {%4,%5,%6,%7}, {%8,%9}, {%0,%1,%2,%3};" \
        : "+f"((c)[0]), "+f"((c)[1]), "+f"((c)[2]), "+f"((c)[3]) \
        : "r"(a0), "r"(a1), "r"(a2), "r"(a3), "r"(b0), "r"(b1))

__device__ __forceinline__ uint32_t packbf2(float x, float y) {
    __nv_bfloat162 h = __floats2bfloat162_rn(x, y);   // x -> low, y -> high
    return *reinterpret_cast<uint32_t*>(&h);
}

// split fp32 fragment into bf16 hi/lo packed fragments (a0,a1,a2,a3 order)
__device__ __forceinline__ void cvt_frag(const float* d, uint32_t* ah, uint32_t* al) {
    const int p0[4] = {0, 4, 2, 6};
    #pragma unroll
    for (int r = 0; r < 4; ++r) {
        float x = d[p0[r]], y = d[p0[r] + 1];
        uint32_t hp = packbf2(x, y);
        float xr = x - __uint_as_float(hp << 16);
        float yr = y - __uint_as_float(hp & 0xFFFF0000u);
        ah[r] = hp;
        al[r] = packbf2(xr, yr);
    }
}

// ============================================================================
// HMMA A-pass v11 (2-term bf16 split, 3 MMAs/product, m16/warp, 8 warps,
// 4-stage cp.async.cg A pipeline, ONE __syncthreads per kstep, depth-2
// issue-ahead, SINGLE-WAVE grid 512 CTAs):
//   Part[z][m][s] = sum_{k in chunk z} A[k,m] * U[k,s]
// ============================================================================
__global__ __launch_bounds__(256, 4) void apass_mma_kernel(
    const float* __restrict__ A,
    const float* __restrict__ U, int ldU,
    float* __restrict__ part)
{
    __shared__ __align__(16) uint8_t sU[4*UT4];    // 18560 B (128 k)
    __shared__ __align__(16) uint8_t sA[4*ABUF];   // 33792 B

    const int tid  = threadIdx.x;
    const int wid  = tid >> 5;
    const int lane = tid & 31;
    const int g    = lane >> 2;
    const int t4   = lane & 3;
    const int m0   = blockIdx.x * 128 + wid * 16;
    const int kz   = blockIdx.y * AP_KCH;
    const uint32_t sUb = smem_u32(sU);
    const uint32_t sAb = smem_u32(sA);

    // ---- A-stage addressing for this thread (2 chunks of 16B per kstep) ----
    const int c0   = tid;
    const int r0c  = c0 >> 5,  q0 = c0 & 31;
    const int r1c  = (c0 + 256) >> 5, q1 = (c0 + 256) & 31;
    const float* gA0 = A + (size_t)(kz + r0c) * NN + blockIdx.x*128 + q0*4;
    const float* gA1 = A + (size_t)(kz + r1c) * NN + blockIdx.x*128 + q1*4;
    const uint32_t dA0 = sAb + (uint32_t)(r0c*AROW + q0*16);
    const uint32_t dA1 = sAb + (uint32_t)(r1c*AROW + q1*16);

    // ---- stage a 128-k U quarter (8 ksteps) as packed b-fragment words ----
    #define STAGE_U(kh) do { \
        _Pragma("unroll") \
        for (int it = 0; it < 4; ++it) { \
            int u  = it * 256 + tid;        /* 0..1023 */ \
            int s  = u & 31; \
            int st_ = (u >> 5) & 7; \
            int tt = u >> 8; \
            int k0 = (kh) + st_*16 + tt*2; \
            float v0 = __ldg(U + (size_t)k0      * ldU + s); \
            float v1 = __ldg(U + (size_t)(k0+1)  * ldU + s); \
            float v2 = __ldg(U + (size_t)(k0+8)  * ldU + s); \
            float v3 = __ldg(U + (size_t)(k0+9)  * ldU + s); \
            uint32_t bh0 = packbf2(v0, v1); \
            uint32_t bl0 = packbf2(v0 - __uint_as_float(bh0 << 16), \
                                   v1 - __uint_as_float(bh0 & 0xFFFF0000u)); \
            uint32_t bh1 = packbf2(v2, v3); \
            uint32_t bl1 = packbf2(v2 - __uint_as_float(bh1 << 16), \
                                   v3 - __uint_as_float(bh1 & 0xFFFF0000u)); \
            uint32_t ad = sUb + tt*UT4 + s*USS + st_*16; \
            STS128U(ad, bh0, bh1, bl0, bl1); \
        } \
    } while (0)

    STAGE_U(kz);

    // ---- accumulators: [nt][4] (m16 per warp) ----
    float c[4][4];
    #pragma unroll
    for (int n = 0; n < 4; ++n)
        #pragma unroll
        for (int i = 0; i < 4; ++i) c[n][i] = 0.f;

    const uint32_t fb = sAb + (uint32_t)(t4*2*AROW + (wid*16 + g)*4);

    // prologue: issue ksteps 0 and 1 as separate groups
    CP_ASYNC16(dA0, gA0);
    CP_ASYNC16(dA1, gA1);
    CP_COMMIT();
    CP_ASYNC16(dA0 + ABUF, gA0 + (size_t)16*NN);
    CP_ASYNC16(dA1 + ABUF, gA1 + (size_t)16*NN);
    CP_COMMIT();

    #pragma unroll 4
    for (int st = 0; st < KSTEPS; ++st) {
        // U quarter boundary: barrier so no warp still reads the old quarter,
        // then restage (published by the main barrier below)
        if (st > 0 && (st & 7) == 0) {
            __syncthreads();
            STAGE_U(kz + st*16);
        }

        // issue two-ahead into buffer (st+2)%4, then wait with 2 in flight
        if (st + 2 < KSTEPS) {
            const uint32_t nb = (uint32_t)(((st + 2) & 3) * ABUF);
            const size_t go = (size_t)(st + 2) * 16 * NN;
            CP_ASYNC16(dA0 + nb, gA0 + go);
            CP_ASYNC16(dA1 + nb, gA1 + go);
            CP_COMMIT();
            CP_WAIT(2);
        } else if (st + 1 < KSTEPS) {
            CP_WAIT(1);
        } else {
            CP_WAIT(0);
        }
        __syncthreads();   // the single per-kstep barrier

        // load the 8 A-fragment scalars from smem (conflict-free LDS.32)
        float d[8];
        const uint32_t b = fb + (uint32_t)((st & 3) * ABUF);
        LDS32F(d[0], b);
        LDS32F(d[1], b + AROW);
        LDS32F(d[2], b + 8*AROW);
        LDS32F(d[3], b + 9*AROW);
        LDS32F(d[4], b + 32);
        LDS32F(d[5], b + AROW + 32);
        LDS32F(d[6], b + 8*AROW + 32);
        LDS32F(d[7], b + 9*AROW + 32);

        uint32_t ah[4], al[4];
        cvt_frag(d, ah, al);

        const uint32_t ub = sUb + t4*UT4 + g*USS + (st & 7)*16;
        #pragma unroll
        for (int nt = 0; nt < 4; ++nt) {
            uint32_t bh0, bh1, bl0, bl1;
            LDS128U(bh0, bh1, bl0, bl1, ub + nt*(8*USS));
            MMA_BF16(c[nt], ah[0],ah[1],ah[2],ah[3], bh0, bh1);
            MMA_BF16(c[nt], ah[0],ah[1],ah[2],ah[3], bl0, bl1);
            MMA_BF16(c[nt], al[0],al[1],al[2],al[3], bh0, bh1);
        }
    }

    // ---- epilogue: C fragment -> Part[z][m][s] ----
    float* pp = part + (size_t)blockIdx.y * (NN*32);
    #pragma unroll
    for (int nt = 0; nt < 4; ++nt) {
        int s = nt*8 + t4*2;
        *(float2*)&pp[(size_t)(m0 + g    )*32 + s] = make_float2(c[nt][0], c[nt][1]);
        *(float2*)&pp[(size_t)(m0 + g + 8)*32 + s] = make_float2(c[nt][2], c[nt][3]);
    }
    #undef STAGE_U
}

// reduce split-K partials (fixed order) into a Ubuf column block (ld=128)
__global__ void reduceU_kernel(float* __restrict__ dst /* Ubuf + colofs */) {
    int i4 = blockIdx.x * blockDim.x + threadIdx.x;   // 65536 float4 slots
    float4 s = make_float4(0.f, 0.f, 0.f, 0.f);
    #pragma unroll
    for (int z = 0; z < AP_SPLITK; ++z) {
        float4 v = *(const float4*)&d_Upart[(size_t)z * (NN*32) + (size_t)i4 * 4];
        s.x += v.x; s.y += v.y; s.z += v.z; s.w += v.w;
    }
    int row = i4 >> 3, c = (i4 & 7) * 4;
    *(float4*)&dst[row*128 + c] = s;
}

// ---------------- generic skinny C = X^T Y kernel (Phi pass) ----------------
template<int MT, int NT, int TJ>
__global__ __launch_bounds__(256) void xty_kernel(
    const float* __restrict__ X, int ldX,
    const float* __restrict__ Y, int ldY,
    float* __restrict__ C, int ldC, int czstride,
    int kchunk)
{
    __shared__ __align__(16) float Xs[TJ*MT];
    __shared__ __align__(16) float Ys[TJ*NT];

    const int tid = threadIdx.x;
    const int m0 = blockIdx.x * MT;
    const int n0 = blockIdx.y * NT;
    const int i_local = tid % MT;
    const int n_base  = (tid / MT) * 8;

    unsigned long long acc0 = 0ull, acc1 = 0ull, acc2 = 0ull, acc3 = 0ull;

    const int ntiles = kchunk / TJ;
    const int kbase = blockIdx.z * kchunk;

    for (int t = 0; t < ntiles; ++t) {
        const int k0 = kbase + t * TJ;
        #pragma unroll
        for (int r = 0; r < (TJ*MT/1024); ++r) {
            int idx = r * 256 + tid;
            int row = idx / (MT/4);
            int c   = idx % (MT/4);
            *(float4*)&Xs[row*MT + c*4] =
                *(const float4*)(X + (size_t)(k0 + row) * ldX + m0 + c*4);
        }
        #pragma unroll
        for (int r = 0; r < (TJ*NT/1024); ++r) {
            int idx = r * 256 + tid;
            int row = idx / (NT/4);
            int c   = idx % (NT/4);
            *(float4*)&Ys[row*NT + c*4] =
                *(const float4*)(Y + (size_t)(k0 + row) * ldY + n0 + c*4);
        }
        __syncthreads();
        #pragma unroll
        for (int j = 0; j < TJ; ++j) {
            float a = Xs[j*MT + i_local];
            unsigned long long a2 = f2pack(a, a);
            const unsigned long long* yp =
                reinterpret_cast<const unsigned long long*>(&Ys[j*NT + n_base]);
            acc0 = f2fma(a2, yp[0], acc0);
            acc1 = f2fma(a2, yp[1], acc1);
            acc2 = f2fma(a2, yp[2], acc2);
            acc3 = f2fma(a2, yp[3], acc3);
        }
        __syncthreads();
    }

    float o[8];
    f2unpack(acc0, o[0], o[1]); f2unpack(acc1, o[2], o[3]);
    f2unpack(acc2, o[4], o[5]); f2unpack(acc3, o[6], o[7]);
    float* cp = C + (size_t)blockIdx.z * czstride
                  + (size_t)(m0 + i_local) * ldC + n0 + n_base;
    *(float4*)cp     = make_float4(o[0], o[1], o[2], o[3]);
    *(float4*)(cp+4) = make_float4(o[4], o[5], o[6], o[7]);
}

// ---------------- copy V into Ubuf columns [0,32) ----------------
__global__ void copyV_kernel(const float* __restrict__ V) {
    int idx = blockIdx.x * blockDim.x + threadIdx.x;   // 65536 float4s
    int i = idx >> 3, c = idx & 7;
    *(float4*)&d_Ubuf[i*128 + c*4] = *(const float4*)(V + i*32 + c*4);
}

// ---- Sherman-Morrison + mixing -> G (32x256); scalars + Phi-reduce fused ----
__global__ void smallmath_kernel(const float* __restrict__ eigvals,
                                 const float* __restrict__ spec_logits,
                                 const float* __restrict__ lap_logits,
                                 const float* __restrict__ hop_weights,
                                 float* __restrict__ out, int out_size)
{
    int s = blockIdx.x;     // 32 blocks
    int d = threadIdx.x;    // 256 threads
    __shared__ float red[256];
    __shared__ float sh_hw[4];
    __shared__ float sh_sw, sh_le;

    if (d < 32) {
        int t = d;
        float sl = spec_logits[t];
        float m = sl;
        #pragma unroll
        for (int o = 16; o; o >>= 1) m = fmaxf(m, __shfl_xor_sync(0xffffffffu, m, o));
        float e = expf(sl - m);
        float ssum = e;
        #pragma unroll
        for (int o = 16; o; o >>= 1) ssum += __shfl_xor_sync(0xffffffffu, ssum, o);
        float sw = e / ssum;
        float x = lap_logits[t];
        float sp = fmaxf(x, 0.f) + log1pf(expf(-fabsf(x)));
        float le = sp * eigvals[t];
        if (t == s) { sh_sw = sw; sh_le = le; }
        float hw = 0.f;
        if (t < 4) {
            float h = hop_weights[t];
            float mh = h;
            #pragma unroll
            for (int o = 2; o; o >>= 1) mh = fmaxf(mh, __shfl_xor_sync(0xFu, mh, o));
            float eh = expf(h - mh);
            float shs = eh;
            #pragma unroll
            for (int o = 2; o; o >>= 1) shs += __shfl_xor_sync(0xFu, shs, o);
            hw = eh / shs;
            sh_hw[t] = hw;
        }
        if (s == 0 && out_size >= ND_TOT + 36) {
            out[ND_TOT + 4 + t] = sw;
            if (t < 4) out[ND_TOT + t] = hw;
        }
    }
    __syncthreads();

    float phv[4], ssk[4];
    #pragma unroll
    for (int k = 0; k < 4; ++k) {
        // fused Phi split-K reduction (fixed order)
        float p = 0.f;
        #pragma unroll
        for (int z = 0; z < KSPLIT_PHI; ++z)
            p += d_PhiPart[z*(128*DD) + (k*32 + s)*DD + d];
        phv[k] = p;
        red[d] = p * p;
        __syncthreads();
        #pragma unroll
        for (int o = 128; o > 0; o >>= 1) {
            if (d < o) red[d] += red[d + o];
            __syncthreads();
        }
        ssk[k] = red[0];
        __syncthreads();
    }
    float qs = 0.f, ps = 0.f;
    #pragma unroll
    for (int k = 0; k < 4; ++k) {
        float q = COEFF_C * phv[k] / (1.f + COEFF_C * ssk[k]);
        qs = fmaf(sh_hw[k], q, qs);
        ps = fmaf(sh_hw[k], phv[k], ps);
    }
    d_G[s*DD + d] = ETA_C * (sh_sw * qs - sh_le * ps);
}

// ---------------- fused update + soft-threshold + LayerNorm ----------------
__global__ __launch_bounds__(256) void final_kernel(
    const float* __restrict__ H, const float* __restrict__ V,
    const float* __restrict__ thr, const float* __restrict__ gamma,
    const float* __restrict__ beta, float* __restrict__ out)
{
    int n = blockIdx.x;      // 8192 rows
    int d = threadIdx.x;     // 256
    __shared__ float vs[32];
    __shared__ float rs1[8], rs2[8];
    if (d < 32) vs[d] = V[n*32 + d];
    __syncthreads();

    float acc = H[(size_t)n*DD + d];
    #pragma unroll
    for (int s = 0; s < 32; ++s) acc = fmaf(vs[s], d_G[s*DD + d], acc);

    float ab = fabsf(acc) - thr[d];
    float y = (ab > 0.f) ? copysignf(ab, acc) : 0.f;

    float s1 = y, s2 = y * y;
    #pragma unroll
    for (int o = 16; o; o >>= 1) {
        s1 += __shfl_xor_sync(0xffffffffu, s1, o);
        s2 += __shfl_xor_sync(0xffffffffu, s2, o);
    }
    int w = d >> 5, l = d & 31;
    if (l == 0) { rs1[w] = s1; rs2[w] = s2; }
    __syncthreads();
    if (d == 0) {
        float a = 0.f, b = 0.f;
        #pragma unroll
        for (int i = 0; i < 8; ++i) { a += rs1[i]; b += rs2[i]; }
        rs1[0] = a; rs2[0] = b;
    }
    __syncthreads();
    float mu  = rs1[0] * (1.f/256.f);
    float var = rs2[0] * (1.f/256.f) - mu * mu;
    out[(size_t)n*DD + d] = (y - mu) * rsqrtf(var + LNEPS_C) * gamma[d] + beta[d];
}

// ---------------- launch ----------------
extern "C" void kernel_launch(void* const* d_in, const int* in_sizes, int n_in,
                              void* d_out, int out_size)
{
    const float* H           = (const float*)d_in[0];
    const float* A           = (const float*)d_in[1];
    const float* V           = (const float*)d_in[2];
    const float* eigvals     = (const float*)d_in[3];
    const float* spec_logits = (const float*)d_in[4];
    const float* lap_logits  = (const float*)d_in[5];
    const float* hop_weights = (const float*)d_in[6];
    const float* thr         = (const float*)d_in[7];
    const float* ln_gamma    = (const float*)d_in[8];
    const float* ln_beta     = (const float*)d_in[9];
    float* out = (float*)d_out;

    float* Ubuf = nullptr;
    float* Upart = nullptr;
    float* PhiPart = nullptr;
    cudaGetSymbolAddress((void**)&Ubuf, d_Ubuf);
    cudaGetSymbolAddress((void**)&Upart, d_Upart);
    cudaGetSymbolAddress((void**)&PhiPart, d_PhiPart);

    // U_0 = V into Ubuf (needed only by the Phi pass)
    copyV_kernel<<<256, 256>>>(V);

    // three HMMA passes: U_{k+1} = A^T U_k  (single-wave grid: 512 CTAs)
    dim3 gA(NN/128, AP_SPLITK);   // (64, 8) = 512 CTAs
    apass_mma_kernel<<<gA, 256>>>(A, V, 32, Upart);
    reduceU_kernel<<<256, 256>>>(Ubuf + 32);
    apass_mma_kernel<<<gA, 256>>>(A, Ubuf + 32, 128, Upart);
    reduceU_kernel<<<256, 256>>>(Ubuf + 64);
    apass_mma_kernel<<<gA, 256>>>(A, Ubuf + 64, 128, Upart);
    reduceU_kernel<<<256, 256>>>(Ubuf + 96);

    // Phi = Ubuf^T H  (128 x 256), 16-way split-K into partials
    dim3 g3(4, 4, KSPLIT_PHI);
    xty_kernel<32,64,64><<<g3, 256>>>(Ubuf, 128, H, DD, PhiPart, DD, 128*DD, NN/KSPLIT_PHI);
    // Sherman-Morrison + scalars + fused Phi-reduce + mixing -> G
    smallmath_kernel<<<32, 256>>>(eigvals, spec_logits, lap_logits, hop_weights,
                                  out, out_size);
    // H_out = LN(softthresh(H + V @ G))
    final_kernel<<<NN, 256>>>(H, V, thr, ln_gamma, ln_beta, out);
}

// round 17
// speedup vs baseline: 1.3643x; 1.1313x over previous
#include <cuda_runtime.h>
#include <cuda_bf16.h>
#include <math.h>
#include <stdint.h>

// Problem constants (fixed shapes)
#define NN 8192
#define DD 256
#define NS 32
#define ND_TOT (NN*DD)
#define COEFF_C 0.125f        // d/(n*EPS^2) = 256/(8192*0.25)
#define ETA_C 0.5f
#define LNEPS_C 1e-5f
#define KSPLIT_PHI 16
#define AP_SPLITK 8
#define AP_KCH 1024           // k per CTA (eight 128-k U quarters)
#define KSTEPS 64             // 16-k MMA steps per CTA

// packed-U smem layout strides (bytes) — covers 128 k (8 steps)
#define USS 144               // s-stride: 8 steps x 16B + 16B pad
#define UT4 4640              // t4-block stride (32*USS=4608, +32 pad; ==32 mod 128)

// A-stage smem layout: [16 k][128 m] fp32, row stride 132 floats (528 B)
#define AROW 528
#define ABUF 8448             // 16 * 528

// ---------------- device scratch (no allocation allowed) ----------------
__device__ float d_Ubuf[NN*128];                 // columns [32k,32k+32) = U_k (cols 0-31 unused)
__device__ float d_Upart[AP_SPLITK*NN*32];       // split-K partials (8MB)
__device__ uint4 d_Afrag[512*512*32];            // bf16-hi A fragments (128MB)
__device__ float d_PhiPart[KSPLIT_PHI*128*DD];   // split-K partials for Phi
__device__ float d_G[NS*DD];                     // fused update matrix

// ---------------- f32x2 packed-FMA helpers (Phi pass) ----------------
__device__ __forceinline__ unsigned long long f2pack(float lo, float hi) {
    unsigned long long r;
    asm("mov.b64 %0, {%1,%2};" : "=l"(r) : "f"(lo), "f"(hi));
    return r;
}
__device__ __forceinline__ void f2unpack(unsigned long long v, float& lo, float& hi) {
    asm("mov.b64 {%0,%1}, %2;" : "=f"(lo), "=f"(hi) : "l"(v));
}
__device__ __forceinline__ unsigned long long f2fma(unsigned long long a,
                                                    unsigned long long b,
                                                    unsigned long long c) {
    unsigned long long d;
    asm("fma.rn.f32x2 %0, %1, %2, %3;" : "=l"(d) : "l"(a), "l"(b), "l"(c));
    return d;
}

// ---------------- smem / cp.async / HMMA helpers ----------------
__device__ __forceinline__ uint32_t smem_u32(const void* p) {
    uint32_t a;
    asm("{ .reg .u64 t; cvta.to.shared.u64 t, %1; cvt.u32.u64 %0, t; }"
        : "=r"(a) : "l"(p));
    return a;
}
#define STS128U(addr, a, b, c, d) \
    asm volatile("st.shared.v4.b32 [%0], {%1,%2,%3,%4};" \
                 :: "r"(addr), "r"(a), "r"(b), "r"(c), "r"(d) : "memory")
#define LDS128U(a, b, c, d, addr) \
    asm volatile("ld.shared.v4.b32 {%0,%1,%2,%3}, [%4];" \
                 : "=r"(a), "=r"(b), "=r"(c), "=r"(d) : "r"(addr))
#define LDS32F(v, addr) \
    asm volatile("ld.shared.f32 %0, [%1];" : "=f"(v) : "r"(addr))

#define CP_ASYNC16(dst, src) \
    asm volatile("cp.async.cg.shared.global [%0], [%1], 16;" \
                 :: "r"(dst), "l"(src) : "memory")
#define CP_COMMIT() asm volatile("cp.async.commit_group;" ::: "memory")
#define CP_WAIT(n)  asm volatile("cp.async.wait_group %0;" :: "n"(n) : "memory")

#define MMA_BF16(c, a0, a1, a2, a3, b0, b1) \
    asm volatile("mma.sync.aligned.m16n8k16.row.col.f32.bf16.bf16.f32 " \
        "{%0,%1,%2,%3}, {%4,%5,%6,%7}, {%8,%9}, {%0,%1,%2,%3};" \
        : "+f"((c)[0]), "+f"((c)[1]), "+f"((c)[2]), "+f"((c)[3]) \
        : "r"(a0), "r"(a1), "r"(a2), "r"(a3), "r"(b0), "r"(b1))

__device__ __forceinline__ uint32_t packbf2(float x, float y) {
    __nv_bfloat162 h = __floats2bfloat162_rn(x, y);   // x -> low, y -> high
    return *reinterpret_cast<uint32_t*>(&h);
}

// split fp32 fragment into bf16 hi/lo packed fragments (a0,a1,a2,a3 order)
__device__ __forceinline__ void cvt_frag(const float* d, uint32_t* ah, uint32_t* al) {
    const int p0[4] = {0, 4, 2, 6};
    #pragma unroll
    for (int r = 0; r < 4; ++r) {
        float x = d[p0[r]], y = d[p0[r] + 1];
        uint32_t hp = packbf2(x, y);
        float xr = x - __uint_as_float(hp << 16);
        float yr = y - __uint_as_float(hp & 0xFFFF0000u);
        ah[r] = hp;
        al[r] = packbf2(xr, yr);
    }
}

// ---- stage a 128-k U quarter (8 ksteps) as packed b-fragment words ----
#define STAGE_U(kh) do { \
    _Pragma("unroll") \
    for (int it = 0; it < 4; ++it) { \
        int u  = it * 256 + tid;        /* 0..1023 */ \
        int s  = u & 31; \
        int st_ = (u >> 5) & 7; \
        int tt = u >> 8; \
        int k0 = (kh) + st_*16 + tt*2; \
        float v0 = __ldg(U + (size_t)k0      * ldU + s); \
        float v1 = __ldg(U + (size_t)(k0+1)  * ldU + s); \
        float v2 = __ldg(U + (size_t)(k0+8)  * ldU + s); \
        float v3 = __ldg(U + (size_t)(k0+9)  * ldU + s); \
        uint32_t bh0 = packbf2(v0, v1); \
        uint32_t bl0 = packbf2(v0 - __uint_as_float(bh0 << 16), \
                               v1 - __uint_as_float(bh0 & 0xFFFF0000u)); \
        uint32_t bh1 = packbf2(v2, v3); \
        uint32_t bl1 = packbf2(v2 - __uint_as_float(bh1 << 16), \
                               v3 - __uint_as_float(bh1 & 0xFFFF0000u)); \
        uint32_t ad = sUb + tt*UT4 + s*USS + st_*16; \
        STS128U(ad, bh0, bh1, bl0, bl1); \
    } \
} while (0)

// ============================================================================
// Pass 1 (exact): HMMA A-pass v11 + bf16-hi a-fragment export.
//   Part[z][m][s] = sum_k A[k,m]*U[k,s];  Afrag[(mt*512+kg)*32+lane] = ah
// ============================================================================
__global__ __launch_bounds__(256, 4) void apass_mma_kernel(
    const float* __restrict__ A,
    const float* __restrict__ U, int ldU,
    float* __restrict__ part,
    uint4* __restrict__ Afrag)
{
    __shared__ __align__(16) uint8_t sU[4*UT4];    // 18560 B (128 k)
    __shared__ __align__(16) uint8_t sA[4*ABUF];   // 33792 B

    const int tid  = threadIdx.x;
    const int wid  = tid >> 5;
    const int lane = tid & 31;
    const int g    = lane >> 2;
    const int t4   = lane & 3;
    const int m0   = blockIdx.x * 128 + wid * 16;
    const int kz   = blockIdx.y * AP_KCH;
    const uint32_t sUb = smem_u32(sU);
    const uint32_t sAb = smem_u32(sA);

    // A-stage addressing (2 chunks of 16B per kstep per thread)
    const int c0   = tid;
    const int r0c  = c0 >> 5,  q0 = c0 & 31;
    const int r1c  = (c0 + 256) >> 5, q1 = (c0 + 256) & 31;
    const float* gA0 = A + (size_t)(kz + r0c) * NN + blockIdx.x*128 + q0*4;
    const float* gA1 = A + (size_t)(kz + r1c) * NN + blockIdx.x*128 + q1*4;
    const uint32_t dA0 = sAb + (uint32_t)(r0c*AROW + q0*16);
    const uint32_t dA1 = sAb + (uint32_t)(r1c*AROW + q1*16);

    STAGE_U(kz);

    float c[4][4];
    #pragma unroll
    for (int n = 0; n < 4; ++n)
        #pragma unroll
        for (int i = 0; i < 4; ++i) c[n][i] = 0.f;

    const uint32_t fb = sAb + (uint32_t)(t4*2*AROW + (wid*16 + g)*4);
    uint4* afp = Afrag + ((size_t)(blockIdx.x*8 + wid)*512 + (kz >> 4))*32 + lane;

    // prologue: issue ksteps 0 and 1 as separate groups
    CP_ASYNC16(dA0, gA0);
    CP_ASYNC16(dA1, gA1);
    CP_COMMIT();
    CP_ASYNC16(dA0 + ABUF, gA0 + (size_t)16*NN);
    CP_ASYNC16(dA1 + ABUF, gA1 + (size_t)16*NN);
    CP_COMMIT();

    #pragma unroll 4
    for (int st = 0; st < KSTEPS; ++st) {
        if (st > 0 && (st & 7) == 0) {
            __syncthreads();
            STAGE_U(kz + st*16);
        }

        if (st + 2 < KSTEPS) {
            const uint32_t nb = (uint32_t)(((st + 2) & 3) * ABUF);
            const size_t go = (size_t)(st + 2) * 16 * NN;
            CP_ASYNC16(dA0 + nb, gA0 + go);
            CP_ASYNC16(dA1 + nb, gA1 + go);
            CP_COMMIT();
            CP_WAIT(2);
        } else if (st + 1 < KSTEPS) {
            CP_WAIT(1);
        } else {
            CP_WAIT(0);
        }
        __syncthreads();

        float d[8];
        const uint32_t b = fb + (uint32_t)((st & 3) * ABUF);
        LDS32F(d[0], b);
        LDS32F(d[1], b + AROW);
        LDS32F(d[2], b + 8*AROW);
        LDS32F(d[3], b + 9*AROW);
        LDS32F(d[4], b + 32);
        LDS32F(d[5], b + AROW + 32);
        LDS32F(d[6], b + 8*AROW + 32);
        LDS32F(d[7], b + 9*AROW + 32);

        uint32_t ah[4], al[4];
        cvt_frag(d, ah, al);

        // export hi fragment for passes 2-3 (coalesced 512B/warp)
        afp[(size_t)st * 32] = make_uint4(ah[0], ah[1], ah[2], ah[3]);

        const uint32_t ub = sUb + t4*UT4 + g*USS + (st & 7)*16;
        #pragma unroll
        for (int nt = 0; nt < 4; ++nt) {
            uint32_t bh0, bh1, bl0, bl1;
            LDS128U(bh0, bh1, bl0, bl1, ub + nt*(8*USS));
            MMA_BF16(c[nt], ah[0],ah[1],ah[2],ah[3], bh0, bh1);
            MMA_BF16(c[nt], ah[0],ah[1],ah[2],ah[3], bl0, bl1);
            MMA_BF16(c[nt], al[0],al[1],al[2],al[3], bh0, bh1);
        }
    }

    float* pp = part + (size_t)blockIdx.y * (NN*32);
    #pragma unroll
    for (int nt = 0; nt < 4; ++nt) {
        int s = nt*8 + t4*2;
        *(float2*)&pp[(size_t)(m0 + g    )*32 + s] = make_float2(c[nt][0], c[nt][1]);
        *(float2*)&pp[(size_t)(m0 + g + 8)*32 + s] = make_float2(c[nt][2], c[nt][3]);
    }
}

// ============================================================================
// Passes 2-3 (lean): consume bf16-hi a-fragments from global (128MB/pass),
// 2 MMAs per product (ah*bh + ah*bl). No cp.async, no per-kstep barrier.
// ============================================================================
__global__ __launch_bounds__(256, 4) void apass_frag_kernel(
    const uint4* __restrict__ Afrag,
    const float* __restrict__ U, int ldU,
    float* __restrict__ part)
{
    __shared__ __align__(16) uint8_t sU[4*UT4];    // 18560 B

    const int tid  = threadIdx.x;
    const int wid  = tid >> 5;
    const int lane = tid & 31;
    const int g    = lane >> 2;
    const int t4   = lane & 3;
    const int m0   = blockIdx.x * 128 + wid * 16;
    const int kz   = blockIdx.y * AP_KCH;
    const uint32_t sUb = smem_u32(sU);

    STAGE_U(kz);
    __syncthreads();

    float c[4][4];
    #pragma unroll
    for (int n = 0; n < 4; ++n)
        #pragma unroll
        for (int i = 0; i < 4; ++i) c[n][i] = 0.f;

    const uint4* ap = Afrag + ((size_t)(blockIdx.x*8 + wid)*512 + (kz >> 4))*32 + lane;

    uint4 abuf[2];
    abuf[0] = __ldg(ap);
    abuf[1] = __ldg(ap + 32);

    #pragma unroll 8
    for (int st = 0; st < KSTEPS; ++st) {
        if (st > 0 && (st & 7) == 0) {
            __syncthreads();               // old quarter reads done
            STAGE_U(kz + st*16);
            __syncthreads();               // new quarter visible
        }

        uint4 a = abuf[st & 1];
        if (st + 2 < KSTEPS) abuf[st & 1] = __ldg(ap + (size_t)(st + 2) * 32);

        const uint32_t ub = sUb + t4*UT4 + g*USS + (st & 7)*16;
        #pragma unroll
        for (int nt = 0; nt < 4; ++nt) {
            uint32_t bh0, bh1, bl0, bl1;
            LDS128U(bh0, bh1, bl0, bl1, ub + nt*(8*USS));
            MMA_BF16(c[nt], a.x, a.y, a.z, a.w, bh0, bh1);
            MMA_BF16(c[nt], a.x, a.y, a.z, a.w, bl0, bl1);
        }
    }

    float* pp = part + (size_t)blockIdx.y * (NN*32);
    #pragma unroll
    for (int nt = 0; nt < 4; ++nt) {
        int s = nt*8 + t4*2;
        *(float2*)&pp[(size_t)(m0 + g    )*32 + s] = make_float2(c[nt][0], c[nt][1]);
        *(float2*)&pp[(size_t)(m0 + g + 8)*32 + s] = make_float2(c[nt][2], c[nt][3]);
    }
}

// reduce split-K partials (fixed order) into a Ubuf column block (ld=128)
__global__ void reduceU_kernel(float* __restrict__ dst /* Ubuf + colofs */) {
    int i4 = blockIdx.x * blockDim.x + threadIdx.x;   // 65536 float4 slots
    float4 s = make_float4(0.f, 0.f, 0.f, 0.f);
    #pragma unroll
    for (int z = 0; z < AP_SPLITK; ++z) {
        float4 v = *(const float4*)&d_Upart[(size_t)z * (NN*32) + (size_t)i4 * 4];
        s.x += v.x; s.y += v.y; s.z += v.z; s.w += v.w;
    }
    int row = i4 >> 3, c = (i4 & 7) * 4;
    *(float4*)&dst[row*128 + c] = s;
}

// ---------------- generic skinny C = X^T Y kernel (Phi pass) ----------------
// blockIdx.x == 0 reads hop-0 rows straight from X0 (= V, ld 32).
template<int MT, int NT, int TJ>
__global__ __launch_bounds__(256) void xty_kernel(
    const float* __restrict__ X, int ldX,
    const float* __restrict__ X0, int ldX0,
    const float* __restrict__ Y, int ldY,
    float* __restrict__ C, int ldC, int czstride,
    int kchunk)
{
    __shared__ __align__(16) float Xs[TJ*MT];
    __shared__ __align__(16) float Ys[TJ*NT];

    const int tid = threadIdx.x;
    const int m0 = blockIdx.x * MT;
    const int n0 = blockIdx.y * NT;
    const int i_local = tid % MT;
    const int n_base  = (tid / MT) * 8;

    const float* Xsrc = (blockIdx.x == 0) ? X0 : X;
    const int ldx     = (blockIdx.x == 0) ? ldX0 : ldX;
    const int mofs    = (blockIdx.x == 0) ? 0 : m0;

    unsigned long long acc0 = 0ull, acc1 = 0ull, acc2 = 0ull, acc3 = 0ull;

    const int ntiles = kchunk / TJ;
    const int kbase = blockIdx.z * kchunk;

    for (int t = 0; t < ntiles; ++t) {
        const int k0 = kbase + t * TJ;
        #pragma unroll
        for (int r = 0; r < (TJ*MT/1024); ++r) {
            int idx = r * 256 + tid;
            int row = idx / (MT/4);
            int c   = idx % (MT/4);
            *(float4*)&Xs[row*MT + c*4] =
                *(const float4*)(Xsrc + (size_t)(k0 + row) * ldx + mofs + c*4);
        }
        #pragma unroll
        for (int r = 0; r < (TJ*NT/1024); ++r) {
            int idx = r * 256 + tid;
            int row = idx / (NT/4);
            int c   = idx % (NT/4);
            *(float4*)&Ys[row*NT + c*4] =
                *(const float4*)(Y + (size_t)(k0 + row) * ldY + n0 + c*4);
        }
        __syncthreads();
        #pragma unroll
        for (int j = 0; j < TJ; ++j) {
            float a = Xs[j*MT + i_local];
            unsigned long long a2 = f2pack(a, a);
            const unsigned long long* yp =
                reinterpret_cast<const unsigned long long*>(&Ys[j*NT + n_base]);
            acc0 = f2fma(a2, yp[0], acc0);
            acc1 = f2fma(a2, yp[1], acc1);
            acc2 = f2fma(a2, yp[2], acc2);
            acc3 = f2fma(a2, yp[3], acc3);
        }
        __syncthreads();
    }

    float o[8];
    f2unpack(acc0, o[0], o[1]); f2unpack(acc1, o[2], o[3]);
    f2unpack(acc2, o[4], o[5]); f2unpack(acc3, o[6], o[7]);
    float* cp = C + (size_t)blockIdx.z * czstride
                  + (size_t)(m0 + i_local) * ldC + n0 + n_base;
    *(float4*)cp     = make_float4(o[0], o[1], o[2], o[3]);
    *(float4*)(cp+4) = make_float4(o[4], o[5], o[6], o[7]);
}

// ---- Sherman-Morrison + mixing -> G (32x256); scalars + Phi-reduce fused ----
__global__ void smallmath_kernel(const float* __restrict__ eigvals,
                                 const float* __restrict__ spec_logits,
                                 const float* __restrict__ lap_logits,
                                 const float* __restrict__ hop_weights,
                                 float* __restrict__ out, int out_size)
{
    int s = blockIdx.x;     // 32 blocks
    int d = threadIdx.x;    // 256 threads
    __shared__ float red[256];
    __shared__ float sh_hw[4];
    __shared__ float sh_sw, sh_le;

    if (d < 32) {
        int t = d;
        float sl = spec_logits[t];
        float m = sl;
        #pragma unroll
        for (int o = 16; o; o >>= 1) m = fmaxf(m, __shfl_xor_sync(0xffffffffu, m, o));
        float e = expf(sl - m);
        float ssum = e;
        #pragma unroll
        for (int o = 16; o; o >>= 1) ssum += __shfl_xor_sync(0xffffffffu, ssum, o);
        float sw = e / ssum;
        float x = lap_logits[t];
        float sp = fmaxf(x, 0.f) + log1pf(expf(-fabsf(x)));
        float le = sp * eigvals[t];
        if (t == s) { sh_sw = sw; sh_le = le; }
        float hw = 0.f;
        if (t < 4) {
            float h = hop_weights[t];
            float mh = h;
            #pragma unroll
            for (int o = 2; o; o >>= 1) mh = fmaxf(mh, __shfl_xor_sync(0xFu, mh, o));
            float eh = expf(h - mh);
            float shs = eh;
            #pragma unroll
            for (int o = 2; o; o >>= 1) shs += __shfl_xor_sync(0xFu, shs, o);
            hw = eh / shs;
            sh_hw[t] = hw;
        }
        if (s == 0 && out_size >= ND_TOT + 36) {
            out[ND_TOT + 4 + t] = sw;
            if (t < 4) out[ND_TOT + t] = hw;
        }
    }
    __syncthreads();

    float phv[4], ssk[4];
    #pragma unroll
    for (int k = 0; k < 4; ++k) {
        float p = 0.f;
        #pragma unroll
        for (int z = 0; z < KSPLIT_PHI; ++z)
            p += d_PhiPart[z*(128*DD) + (k*32 + s)*DD + d];
        phv[k] = p;
        red[d] = p * p;
        __syncthreads();
        #pragma unroll
        for (int o = 128; o > 0; o >>= 1) {
            if (d < o) red[d] += red[d + o];
            __syncthreads();
        }
        ssk[k] = red[0];
        __syncthreads();
    }
    float qs = 0.f, ps = 0.f;
    #pragma unroll
    for (int k = 0; k < 4; ++k) {
        float q = COEFF_C * phv[k] / (1.f + COEFF_C * ssk[k]);
        qs = fmaf(sh_hw[k], q, qs);
        ps = fmaf(sh_hw[k], phv[k], ps);
    }
    d_G[s*DD + d] = ETA_C * (sh_sw * qs - sh_le * ps);
}

// ---------------- fused update + soft-threshold + LayerNorm ----------------
__global__ __launch_bounds__(256) void final_kernel(
    const float* __restrict__ H, const float* __restrict__ V,
    const float* __restrict__ thr, const float* __restrict__ gamma,
    const float* __restrict__ beta, float* __restrict__ out)
{
    int n = blockIdx.x;      // 8192 rows
    int d = threadIdx.x;     // 256
    __shared__ float vs[32];
    __shared__ float rs1[8], rs2[8];
    if (d < 32) vs[d] = V[n*32 + d];
    __syncthreads();

    float acc = H[(size_t)n*DD + d];
    #pragma unroll
    for (int s = 0; s < 32; ++s) acc = fmaf(vs[s], d_G[s*DD + d], acc);

    float ab = fabsf(acc) - thr[d];
    float y = (ab > 0.f) ? copysignf(ab, acc) : 0.f;

    float s1 = y, s2 = y * y;
    #pragma unroll
    for (int o = 16; o; o >>= 1) {
        s1 += __shfl_xor_sync(0xffffffffu, s1, o);
        s2 += __shfl_xor_sync(0xffffffffu, s2, o);
    }
    int w = d >> 5, l = d & 31;
    if (l == 0) { rs1[w] = s1; rs2[w] = s2; }
    __syncthreads();
    if (d == 0) {
        float a = 0.f, b = 0.f;
        #pragma unroll
        for (int i = 0; i < 8; ++i) { a += rs1[i]; b += rs2[i]; }
        rs1[0] = a; rs2[0] = b;
    }
    __syncthreads();
    float mu  = rs1[0] * (1.f/256.f);
    float var = rs2[0] * (1.f/256.f) - mu * mu;
    out[(size_t)n*DD + d] = (y - mu) * rsqrtf(var + LNEPS_C) * gamma[d] + beta[d];
}

// ---------------- launch ----------------
extern "C" void kernel_launch(void* const* d_in, const int* in_sizes, int n_in,
                              void* d_out, int out_size)
{
    const float* H           = (const float*)d_in[0];
    const float* A           = (const float*)d_in[1];
    const float* V           = (const float*)d_in[2];
    const float* eigvals     = (const float*)d_in[3];
    const float* spec_logits = (const float*)d_in[4];
    const float* lap_logits  = (const float*)d_in[5];
    const float* hop_weights = (const float*)d_in[6];
    const float* thr         = (const float*)d_in[7];
    const float* ln_gamma    = (const float*)d_in[8];
    const float* ln_beta     = (const float*)d_in[9];
    float* out = (float*)d_out;

    float* Ubuf = nullptr;
    float* Upart = nullptr;
    uint4* Afrag = nullptr;
    float* PhiPart = nullptr;
    cudaGetSymbolAddress((void**)&Ubuf, d_Ubuf);
    cudaGetSymbolAddress((void**)&Upart, d_Upart);
    cudaGetSymbolAddress((void**)&Afrag, d_Afrag);
    cudaGetSymbolAddress((void**)&PhiPart, d_PhiPart);

    // pass 1 (exact, exports bf16-hi a-fragments), then lean passes 2-3
    dim3 gA(NN/128, AP_SPLITK);   // (64, 8) = 512 CTAs (single wave)
    apass_mma_kernel<<<gA, 256>>>(A, V, 32, Upart, Afrag);
    reduceU_kernel<<<256, 256>>>(Ubuf + 32);
    apass_frag_kernel<<<gA, 256>>>(Afrag, Ubuf + 32, 128, Upart);
    reduceU_kernel<<<256, 256>>>(Ubuf + 64);
    apass_frag_kernel<<<gA, 256>>>(Afrag, Ubuf + 64, 128, Upart);
    reduceU_kernel<<<256, 256>>>(Ubuf + 96);

    // Phi = [V | U1 U2 U3]^T H  (hop-0 block reads V directly)
    dim3 g3(4, 4, KSPLIT_PHI);
    xty_kernel<32,64,64><<<g3, 256>>>(Ubuf, 128, V, 32, H, DD,
                                      PhiPart, DD, 128*DD, NN/KSPLIT_PHI);
    // Sherman-Morrison + scalars + fused Phi-reduce + mixing -> G
    smallmath_kernel<<<32, 256>>>(eigvals, spec_logits, lap_logits, hop_weights,
                                  out, out_size);
    // H_out = LN(softthresh(H + V @ G))
    final_kernel<<<NN, 256>>>(H, V, thr, ln_gamma, ln_beta, out);
}